// round 1
// baseline (speedup 1.0000x reference)
#include <cuda_runtime.h>

// Problem constants
#define M_TOTAL 4608          // 2 * 48 * 48 pixels
#define D_MODEL 512
#define QKV_N   1536
#define N_HEADS 8
#define D_HEAD  64
#define KS      7
#define HW      48

// Scratch (device globals: allocation-free contract)
__device__ float g_qkv[M_TOTAL * QKV_N];   // (pixel, 3*512): [q | k | v], each head-major
__device__ float g_att[M_TOTAL * D_MODEL]; // attention output, (pixel, g*64+e)

// ---------------------------------------------------------------------------
// 64x64x16 fp32 tiled GEMM, 256 threads, 4x4 microtile per thread.
// C[M,N] = A[M,K] @ B[K,N], all row-major. Dims must be multiples of 64/64/16.
// ---------------------------------------------------------------------------
__global__ __launch_bounds__(256) void sgemm64(const float* __restrict__ A,
                                               const float* __restrict__ B,
                                               float* __restrict__ C,
                                               int M, int N, int K) {
    __shared__ float As[16][64];   // As[k][m]
    __shared__ float Bs[16][64];   // Bs[k][n]

    const int t  = threadIdx.x;
    const int tx = t & 15;
    const int ty = t >> 4;
    const int row0 = blockIdx.y * 64;
    const int col0 = blockIdx.x * 64;

    // A tile load mapping: element e = t*4 .. t*4+3 -> (m = e>>4, k = e&15)
    const int ai = t >> 2;          // row within A tile, 0..63
    const int aj = (t & 3) * 4;     // k within tile, 0/4/8/12
    // B tile load mapping: (k = t>>4, n = (t&15)*4)
    const int bi = t >> 4;
    const int bj = (t & 15) * 4;

    float acc[4][4];
#pragma unroll
    for (int i = 0; i < 4; ++i)
#pragma unroll
        for (int j = 0; j < 4; ++j) acc[i][j] = 0.f;

    for (int k0 = 0; k0 < K; k0 += 16) {
        float4 av = *(const float4*)&A[(size_t)(row0 + ai) * K + k0 + aj];
        As[aj + 0][ai] = av.x;
        As[aj + 1][ai] = av.y;
        As[aj + 2][ai] = av.z;
        As[aj + 3][ai] = av.w;
        float4 bv = *(const float4*)&B[(size_t)(k0 + bi) * N + col0 + bj];
        *(float4*)&Bs[bi][bj] = bv;
        __syncthreads();

#pragma unroll
        for (int kk = 0; kk < 16; ++kk) {
            float4 a = *(const float4*)&As[kk][ty * 4];
            float4 b = *(const float4*)&Bs[kk][tx * 4];
            acc[0][0] += a.x * b.x; acc[0][1] += a.x * b.y; acc[0][2] += a.x * b.z; acc[0][3] += a.x * b.w;
            acc[1][0] += a.y * b.x; acc[1][1] += a.y * b.y; acc[1][2] += a.y * b.z; acc[1][3] += a.y * b.w;
            acc[2][0] += a.z * b.x; acc[2][1] += a.z * b.y; acc[2][2] += a.z * b.z; acc[2][3] += a.z * b.w;
            acc[3][0] += a.w * b.x; acc[3][1] += a.w * b.y; acc[3][2] += a.w * b.z; acc[3][3] += a.w * b.w;
        }
        __syncthreads();
    }

#pragma unroll
    for (int i = 0; i < 4; ++i) {
        float4 r = make_float4(acc[i][0], acc[i][1], acc[i][2], acc[i][3]);
        *(float4*)&C[(size_t)(row0 + ty * 4 + i) * N + col0 + tx * 4] = r;
    }
}

// ---------------------------------------------------------------------------
// Neighborhood attention: one warp per (pixel, head).
// qkv layout per pixel: [ q(8 heads x 64) | k(8x64) | v(8x64) ]
// ---------------------------------------------------------------------------
__global__ __launch_bounds__(256) void natten_kernel(const float* __restrict__ qkv,
                                                     float* __restrict__ out) {
    const int gwarp = (blockIdx.x * blockDim.x + threadIdx.x) >> 5;
    const int lane  = threadIdx.x & 31;
    if (gwarp >= M_TOTAL * N_HEADS) return;

    const int g   = gwarp & (N_HEADS - 1);
    const int pix = gwarp >> 3;
    const int n   = pix / (HW * HW);
    const int r   = pix % (HW * HW);
    const int y   = r / HW;
    const int x   = r % HW;

    const int sy = min(max(y - KS / 2, 0), HW - KS);
    const int sx = min(max(x - KS / 2, 0), HW - KS);

    // q: each lane holds 2 elements
    const float* qp = qkv + (size_t)pix * QKV_N + g * D_HEAD + lane * 2;
    const float2 q = *(const float2*)qp;

    const float* kbase = qkv + (size_t)n * (HW * HW) * QKV_N + D_MODEL + g * D_HEAD + lane * 2;

    float lg[KS * KS];
#pragma unroll
    for (int a = 0; a < KS; ++a) {
#pragma unroll
        for (int b = 0; b < KS; ++b) {
            const int m2 = (sy + a) * HW + (sx + b);
            const float2 kv = *(const float2*)(kbase + (size_t)m2 * QKV_N);
            float p = q.x * kv.x + q.y * kv.y;
            p += __shfl_xor_sync(0xffffffffu, p, 16);
            p += __shfl_xor_sync(0xffffffffu, p, 8);
            p += __shfl_xor_sync(0xffffffffu, p, 4);
            p += __shfl_xor_sync(0xffffffffu, p, 2);
            p += __shfl_xor_sync(0xffffffffu, p, 1);
            lg[a * KS + b] = p * 0.125f;  // 1/sqrt(64)
        }
    }

    float mx = lg[0];
#pragma unroll
    for (int j = 1; j < KS * KS; ++j) mx = fmaxf(mx, lg[j]);

    float s = 0.f;
#pragma unroll
    for (int j = 0; j < KS * KS; ++j) {
        lg[j] = __expf(lg[j] - mx);
        s += lg[j];
    }
    const float inv = 1.f / s;

    const float* vbase = kbase + D_MODEL;  // v is 512 floats after k
    float o0 = 0.f, o1 = 0.f;
#pragma unroll
    for (int a = 0; a < KS; ++a) {
#pragma unroll
        for (int b = 0; b < KS; ++b) {
            const int m2 = (sy + a) * HW + (sx + b);
            const float2 vv = *(const float2*)(vbase + (size_t)m2 * QKV_N);
            const float p = lg[a * KS + b];
            o0 += p * vv.x;
            o1 += p * vv.y;
        }
    }

    float2 res = make_float2(o0 * inv, o1 * inv);
    *(float2*)(out + (size_t)pix * D_MODEL + g * D_HEAD + lane * 2) = res;
}

// ---------------------------------------------------------------------------
extern "C" void kernel_launch(void* const* d_in, const int* in_sizes, int n_in,
                              void* d_out, int out_size) {
    const float* x     = (const float*)d_in[0];   // (2,48,48,512)
    const float* w_qkv = (const float*)d_in[1];   // (512,1536)
    const float* w_out = (const float*)d_in[2];   // (512,512)
    float* out = (float*)d_out;                   // (2,48,48,512)

    float* qkv = nullptr;
    float* att = nullptr;
    cudaGetSymbolAddress((void**)&qkv, g_qkv);
    cudaGetSymbolAddress((void**)&att, g_att);

    // 1) QKV projection: (4608,512) @ (512,1536)
    sgemm64<<<dim3(QKV_N / 64, M_TOTAL / 64), 256>>>(x, w_qkv, qkv, M_TOTAL, QKV_N, D_MODEL);

    // 2) Neighborhood attention: 36864 warps, 8 per block
    natten_kernel<<<M_TOTAL, 256>>>(qkv, att);

    // 3) Output projection: (4608,512) @ (512,512)
    sgemm64<<<dim3(D_MODEL / 64, M_TOTAL / 64), 256>>>(att, w_out, out, M_TOTAL, D_MODEL, D_MODEL);
}

// round 2
// speedup vs baseline: 2.4193x; 2.4193x over previous
#include <cuda_runtime.h>
#include <cstdint>

// Problem constants
#define M_TOTAL 4608          // 2 * 48 * 48 pixels
#define D_MODEL 512
#define QKV_N   1536
#define N_HEADS 8
#define D_HEAD  64
#define KS      7
#define HW      48

// Scratch (device globals: allocation-free contract)
__device__ float g_qkv[M_TOTAL * QKV_N];   // (pixel, 3*512): [q | k | v]
__device__ float g_att[M_TOTAL * D_MODEL]; // attention output

// ---------------------------------------------------------------------------
// cp.async helpers
// ---------------------------------------------------------------------------
__device__ __forceinline__ void cp_async16(float* smem_dst, const float* gmem_src) {
    unsigned s = (unsigned)__cvta_generic_to_shared(smem_dst);
    asm volatile("cp.async.cg.shared.global [%0], [%1], 16;" :: "r"(s), "l"(gmem_src));
}
__device__ __forceinline__ void cp_commit() {
    asm volatile("cp.async.commit_group;");
}
template <int N>
__device__ __forceinline__ void cp_wait() {
    asm volatile("cp.async.wait_group %0;" :: "n"(N));
}
__device__ __forceinline__ uint32_t f2tf32(float f) {
    uint32_t u;
    asm("cvt.rna.tf32.f32 %0, %1;" : "=r"(u) : "f"(f));
    return u;
}
__device__ __forceinline__ void mma_tf32(float c[4], const uint32_t a[4], const uint32_t b[2]) {
    asm volatile(
        "mma.sync.aligned.m16n8k8.row.col.f32.tf32.tf32.f32 "
        "{%0,%1,%2,%3}, {%4,%5,%6,%7}, {%8,%9}, {%0,%1,%2,%3};"
        : "+f"(c[0]), "+f"(c[1]), "+f"(c[2]), "+f"(c[3])
        : "r"(a[0]), "r"(a[1]), "r"(a[2]), "r"(a[3]), "r"(b[0]), "r"(b[1]));
}

// ---------------------------------------------------------------------------
// TF32 tensor-core GEMM: C[M,N] = A[M,K] @ B[K,N], row-major.
// Block tile 128x128x32, 256 threads (8 warps = 4m x 2n), warp tile 32x64.
// Dims must be multiples of 128/128/32.
// Smem: A [128][36] (pad->conflict-free frag LDS), B [32][136].
// ---------------------------------------------------------------------------
#define A_STRIDE 36
#define B_STRIDE 136
#define STAGE_FLOATS (128 * A_STRIDE + 32 * B_STRIDE)   // 4608 + 4352 = 8960

__global__ __launch_bounds__(256) void tgemm128(const float* __restrict__ A,
                                                const float* __restrict__ B,
                                                float* __restrict__ C,
                                                int M, int N, int K) {
    extern __shared__ float smem[];

    const int t      = threadIdx.x;
    const int lane   = t & 31;
    const int wid    = t >> 5;
    const int warp_m = wid >> 1;      // 0..3
    const int warp_n = wid & 1;       // 0..1
    const int c_lane = lane & 3;      // k quad
    const int r_lane = lane >> 2;     // row/col octet

    const int row0 = blockIdx.y * 128;
    const int col0 = blockIdx.x * 128;

    // Global->smem load mappings (float4 granularity, 4 per thread per tile)
    // A: f4 idx i: arow = i>>3, acol = (i&7)*4
    // B: f4 idx i: brow = i>>5, bcol = (i&31)*4
    const int NT = K / 32;

    auto load_tile = [&](int tile, int stage) {
        float* As = smem + stage * STAGE_FLOATS;
        float* Bs = As + 128 * A_STRIDE;
        const float* gA = A + (size_t)row0 * K + tile * 32;
        const float* gB = B + (size_t)(tile * 32) * N + col0;
#pragma unroll
        for (int u = 0; u < 4; ++u) {
            int i = t + u * 256;
            int arow = i >> 3, acol = (i & 7) * 4;
            cp_async16(&As[arow * A_STRIDE + acol], gA + (size_t)arow * K + acol);
        }
#pragma unroll
        for (int u = 0; u < 4; ++u) {
            int i = t + u * 256;
            int brow = i >> 5, bcol = (i & 31) * 4;
            cp_async16(&Bs[brow * B_STRIDE + bcol], gB + (size_t)brow * N + bcol);
        }
        cp_commit();
    };

    float acc[2][8][4];
#pragma unroll
    for (int mt = 0; mt < 2; ++mt)
#pragma unroll
        for (int nt = 0; nt < 8; ++nt)
#pragma unroll
            for (int j = 0; j < 4; ++j) acc[mt][nt][j] = 0.f;

    load_tile(0, 0);

    for (int tile = 0; tile < NT; ++tile) {
        const int stage = tile & 1;
        if (tile + 1 < NT) {
            load_tile(tile + 1, stage ^ 1);
            cp_wait<1>();
        } else {
            cp_wait<0>();
        }
        __syncthreads();

        const float* As = smem + stage * STAGE_FLOATS;
        const float* Bs = As + 128 * A_STRIDE;

#pragma unroll
        for (int ks = 0; ks < 4; ++ks) {
            const int kb = ks * 8;
            uint32_t af[2][4];
#pragma unroll
            for (int mt = 0; mt < 2; ++mt) {
                const int row = warp_m * 32 + mt * 16 + r_lane;
                af[mt][0] = f2tf32(As[row * A_STRIDE + kb + c_lane]);
                af[mt][1] = f2tf32(As[(row + 8) * A_STRIDE + kb + c_lane]);
                af[mt][2] = f2tf32(As[row * A_STRIDE + kb + 4 + c_lane]);
                af[mt][3] = f2tf32(As[(row + 8) * A_STRIDE + kb + 4 + c_lane]);
            }
            uint32_t bf[8][2];
#pragma unroll
            for (int nt = 0; nt < 8; ++nt) {
                const int col = warp_n * 64 + nt * 8 + r_lane;
                bf[nt][0] = f2tf32(Bs[(kb + c_lane) * B_STRIDE + col]);
                bf[nt][1] = f2tf32(Bs[(kb + 4 + c_lane) * B_STRIDE + col]);
            }
#pragma unroll
            for (int mt = 0; mt < 2; ++mt)
#pragma unroll
                for (int nt = 0; nt < 8; ++nt)
                    mma_tf32(acc[mt][nt], af[mt], bf[nt]);
        }
        __syncthreads();
    }

    // Epilogue: c0/c1 at (row, 2c), (row, 2c+1); c2/c3 at (row+8, ...)
#pragma unroll
    for (int mt = 0; mt < 2; ++mt) {
        const int row_g = row0 + warp_m * 32 + mt * 16 + r_lane;
#pragma unroll
        for (int nt = 0; nt < 8; ++nt) {
            const int col_g = col0 + warp_n * 64 + nt * 8 + 2 * c_lane;
            *(float2*)&C[(size_t)row_g * N + col_g] =
                make_float2(acc[mt][nt][0], acc[mt][nt][1]);
            *(float2*)&C[(size_t)(row_g + 8) * N + col_g] =
                make_float2(acc[mt][nt][2], acc[mt][nt][3]);
        }
    }
}

// ---------------------------------------------------------------------------
// Neighborhood attention: one warp per (pixel, head).  (unchanged from R1)
// ---------------------------------------------------------------------------
__global__ __launch_bounds__(256) void natten_kernel(const float* __restrict__ qkv,
                                                     float* __restrict__ out) {
    const int gwarp = (blockIdx.x * blockDim.x + threadIdx.x) >> 5;
    const int lane  = threadIdx.x & 31;
    if (gwarp >= M_TOTAL * N_HEADS) return;

    const int g   = gwarp & (N_HEADS - 1);
    const int pix = gwarp >> 3;
    const int n   = pix / (HW * HW);
    const int r   = pix % (HW * HW);
    const int y   = r / HW;
    const int x   = r % HW;

    const int sy = min(max(y - KS / 2, 0), HW - KS);
    const int sx = min(max(x - KS / 2, 0), HW - KS);

    const float* qp = qkv + (size_t)pix * QKV_N + g * D_HEAD + lane * 2;
    const float2 q = *(const float2*)qp;

    const float* kbase = qkv + (size_t)n * (HW * HW) * QKV_N + D_MODEL + g * D_HEAD + lane * 2;

    float lg[KS * KS];
#pragma unroll
    for (int a = 0; a < KS; ++a) {
#pragma unroll
        for (int b = 0; b < KS; ++b) {
            const int m2 = (sy + a) * HW + (sx + b);
            const float2 kv = *(const float2*)(kbase + (size_t)m2 * QKV_N);
            float p = q.x * kv.x + q.y * kv.y;
            p += __shfl_xor_sync(0xffffffffu, p, 16);
            p += __shfl_xor_sync(0xffffffffu, p, 8);
            p += __shfl_xor_sync(0xffffffffu, p, 4);
            p += __shfl_xor_sync(0xffffffffu, p, 2);
            p += __shfl_xor_sync(0xffffffffu, p, 1);
            lg[a * KS + b] = p * 0.125f;  // 1/sqrt(64)
        }
    }

    float mx = lg[0];
#pragma unroll
    for (int j = 1; j < KS * KS; ++j) mx = fmaxf(mx, lg[j]);

    float s = 0.f;
#pragma unroll
    for (int j = 0; j < KS * KS; ++j) {
        lg[j] = __expf(lg[j] - mx);
        s += lg[j];
    }
    const float inv = 1.f / s;

    const float* vbase = kbase + D_MODEL;
    float o0 = 0.f, o1 = 0.f;
#pragma unroll
    for (int a = 0; a < KS; ++a) {
#pragma unroll
        for (int b = 0; b < KS; ++b) {
            const int m2 = (sy + a) * HW + (sx + b);
            const float2 vv = *(const float2*)(vbase + (size_t)m2 * QKV_N);
            const float p = lg[a * KS + b];
            o0 += p * vv.x;
            o1 += p * vv.y;
        }
    }

    float2 res = make_float2(o0 * inv, o1 * inv);
    *(float2*)(out + (size_t)pix * D_MODEL + g * D_HEAD + lane * 2) = res;
}

// ---------------------------------------------------------------------------
extern "C" void kernel_launch(void* const* d_in, const int* in_sizes, int n_in,
                              void* d_out, int out_size) {
    const float* x     = (const float*)d_in[0];   // (2,48,48,512)
    const float* w_qkv = (const float*)d_in[1];   // (512,1536)
    const float* w_out = (const float*)d_in[2];   // (512,512)
    float* out = (float*)d_out;                   // (2,48,48,512)

    float* qkv = nullptr;
    float* att = nullptr;
    cudaGetSymbolAddress((void**)&qkv, g_qkv);
    cudaGetSymbolAddress((void**)&att, g_att);

    const int smem_bytes = 2 * STAGE_FLOATS * sizeof(float);  // 71680
    static bool attr_set = false;
    if (!attr_set) {
        cudaFuncSetAttribute(tgemm128, cudaFuncAttributeMaxDynamicSharedMemorySize, smem_bytes);
        attr_set = true;
    }

    // 1) QKV projection: (4608,512) @ (512,1536)
    tgemm128<<<dim3(QKV_N / 128, M_TOTAL / 128), 256, smem_bytes>>>(
        x, w_qkv, qkv, M_TOTAL, QKV_N, D_MODEL);

    // 2) Neighborhood attention
    natten_kernel<<<M_TOTAL, 256>>>(qkv, att);

    // 3) Output projection: (4608,512) @ (512,512)
    tgemm128<<<dim3(D_MODEL / 128, M_TOTAL / 128), 256, smem_bytes>>>(
        att, w_out, out, M_TOTAL, D_MODEL, D_MODEL);
}

// round 3
// speedup vs baseline: 2.4279x; 1.0036x over previous
#include <cuda_runtime.h>
#include <cstdint>

#define M_TOTAL 4608          // 2 * 48 * 48 pixels
#define D_MODEL 512
#define QKV_N   1536
#define N_HEADS 8
#define D_HEAD  64
#define KS      7
#define HW      48
#define IMG_PIX (HW * HW)     // 2304
#define PLANE   (IMG_PIX * D_HEAD)   // 147456 floats per (n,g) plane

// Scratch (device globals: allocation-free contract)
// Layout: q planes [2*8][2304][64], then k planes, then v planes.
__device__ float g_qkv[M_TOTAL * QKV_N];
__device__ float g_att[M_TOTAL * D_MODEL];

#define K_OFF ((size_t)M_TOTAL * 512)
#define V_OFF ((size_t)M_TOTAL * 1024)

// ---------------------------------------------------------------------------
__device__ __forceinline__ void cp_async16(float* smem_dst, const float* gmem_src) {
    unsigned s = (unsigned)__cvta_generic_to_shared(smem_dst);
    asm volatile("cp.async.cg.shared.global [%0], [%1], 16;" :: "r"(s), "l"(gmem_src));
}
__device__ __forceinline__ void cp_commit() { asm volatile("cp.async.commit_group;"); }
template <int N>
__device__ __forceinline__ void cp_wait() { asm volatile("cp.async.wait_group %0;" :: "n"(N)); }
__device__ __forceinline__ uint32_t f2tf32(float f) {
    uint32_t u;
    asm("cvt.rna.tf32.f32 %0, %1;" : "=r"(u) : "f"(f));
    return u;
}
__device__ __forceinline__ void mma_tf32(float c[4], const uint32_t a[4], const uint32_t b[2]) {
    asm volatile(
        "mma.sync.aligned.m16n8k8.row.col.f32.tf32.tf32.f32 "
        "{%0,%1,%2,%3}, {%4,%5,%6,%7}, {%8,%9}, {%0,%1,%2,%3};"
        : "+f"(c[0]), "+f"(c[1]), "+f"(c[2]), "+f"(c[3])
        : "r"(a[0]), "r"(a[1]), "r"(a[2]), "r"(a[3]), "r"(b[0]), "r"(b[1]));
}

// ---------------------------------------------------------------------------
// TF32 tensor-core GEMM, 128x128x32 tile, 256 threads, double-buffered cp.async.
// SCATTER=true: writes into per-(image,head) q/k/v planes instead of row-major C.
// ---------------------------------------------------------------------------
#define A_STRIDE 36
#define B_STRIDE 136
#define STAGE_FLOATS (128 * A_STRIDE + 32 * B_STRIDE)   // 8960

template <bool SCATTER>
__global__ __launch_bounds__(256, 2) void tgemm128(const float* __restrict__ A,
                                                   const float* __restrict__ B,
                                                   float* __restrict__ C,
                                                   int M, int N, int K) {
    extern __shared__ float smem[];

    const int t      = threadIdx.x;
    const int lane   = t & 31;
    const int wid    = t >> 5;
    const int warp_m = wid >> 1;
    const int warp_n = wid & 1;
    const int c_lane = lane & 3;
    const int r_lane = lane >> 2;

    const int row0 = blockIdx.y * 128;
    const int col0 = blockIdx.x * 128;
    const int NT = K / 32;

    auto load_tile = [&](int tile, int stage) {
        float* As = smem + stage * STAGE_FLOATS;
        float* Bs = As + 128 * A_STRIDE;
        const float* gA = A + (size_t)row0 * K + tile * 32;
        const float* gB = B + (size_t)(tile * 32) * N + col0;
#pragma unroll
        for (int u = 0; u < 4; ++u) {
            int i = t + u * 256;
            int arow = i >> 3, acol = (i & 7) * 4;
            cp_async16(&As[arow * A_STRIDE + acol], gA + (size_t)arow * K + acol);
        }
#pragma unroll
        for (int u = 0; u < 4; ++u) {
            int i = t + u * 256;
            int brow = i >> 5, bcol = (i & 31) * 4;
            cp_async16(&Bs[brow * B_STRIDE + bcol], gB + (size_t)brow * N + bcol);
        }
        cp_commit();
    };

    float acc[2][8][4];
#pragma unroll
    for (int mt = 0; mt < 2; ++mt)
#pragma unroll
        for (int nt = 0; nt < 8; ++nt)
#pragma unroll
            for (int j = 0; j < 4; ++j) acc[mt][nt][j] = 0.f;

    load_tile(0, 0);

    for (int tile = 0; tile < NT; ++tile) {
        const int stage = tile & 1;
        if (tile + 1 < NT) {
            load_tile(tile + 1, stage ^ 1);
            cp_wait<1>();
        } else {
            cp_wait<0>();
        }
        __syncthreads();

        const float* As = smem + stage * STAGE_FLOATS;
        const float* Bs = As + 128 * A_STRIDE;

#pragma unroll
        for (int ks = 0; ks < 4; ++ks) {
            const int kb = ks * 8;
            uint32_t af[2][4];
#pragma unroll
            for (int mt = 0; mt < 2; ++mt) {
                const int row = warp_m * 32 + mt * 16 + r_lane;
                af[mt][0] = f2tf32(As[row * A_STRIDE + kb + c_lane]);
                af[mt][1] = f2tf32(As[(row + 8) * A_STRIDE + kb + c_lane]);
                af[mt][2] = f2tf32(As[row * A_STRIDE + kb + 4 + c_lane]);
                af[mt][3] = f2tf32(As[(row + 8) * A_STRIDE + kb + 4 + c_lane]);
            }
            uint32_t bf[8][2];
#pragma unroll
            for (int nt = 0; nt < 8; ++nt) {
                const int col = warp_n * 64 + nt * 8 + r_lane;
                bf[nt][0] = f2tf32(Bs[(kb + c_lane) * B_STRIDE + col]);
                bf[nt][1] = f2tf32(Bs[(kb + 4 + c_lane) * B_STRIDE + col]);
            }
#pragma unroll
            for (int mt = 0; mt < 2; ++mt)
#pragma unroll
                for (int nt = 0; nt < 8; ++nt)
                    mma_tf32(acc[mt][nt], af[mt], bf[nt]);
        }
        __syncthreads();
    }

    // Epilogue
    const int img_n = row0 >= IMG_PIX;   // 2304 is a multiple of 128: whole block same image
#pragma unroll
    for (int mt = 0; mt < 2; ++mt) {
        const int row_g = row0 + warp_m * 32 + mt * 16 + r_lane;
#pragma unroll
        for (int nt = 0; nt < 8; ++nt) {
            const int col_g = col0 + warp_n * 64 + nt * 8 + 2 * c_lane;
            if (!SCATTER) {
                *(float2*)&C[(size_t)row_g * N + col_g] =
                    make_float2(acc[mt][nt][0], acc[mt][nt][1]);
                *(float2*)&C[(size_t)(row_g + 8) * N + col_g] =
                    make_float2(acc[mt][nt][2], acc[mt][nt][3]);
            } else {
                const int which = col_g >> 9;            // 0=q, 1=k, 2=v
                const int g     = (col_g >> 6) & 7;
                const int e     = col_g & 63;
                const int p     = row_g - img_n * IMG_PIX;
                float* dst = C + (size_t)which * K_OFF +
                             ((size_t)(img_n * 8 + g) * IMG_PIX + p) * 64 + e;
                *(float2*)dst = make_float2(acc[mt][nt][0], acc[mt][nt][1]);
                *(float2*)(dst + 8 * 64) = make_float2(acc[mt][nt][2], acc[mt][nt][3]);
            }
        }
    }
}

// ---------------------------------------------------------------------------
// Smem-tiled neighborhood attention.
// Block = 8x8 pixel tile, one head. 14x14 K/V halo staged in shared memory.
// 8 warps: warp w handles tile row w (8 pixels).
// ---------------------------------------------------------------------------
#define HALO 14
#define NATTEN_SMEM (2 * HALO * HALO * D_HEAD * sizeof(float))   // 100352 B

__global__ __launch_bounds__(256) void natten2(const float* __restrict__ qkv,
                                               float* __restrict__ out) {
    extern __shared__ float sh[];
    float* kh = sh;                           // [196][64]
    float* vh = sh + HALO * HALO * D_HEAD;    // [196][64]

    const int tx0 = blockIdx.x * 8;
    const int ty0 = blockIdx.y * 8;
    const int z   = blockIdx.z;               // n*8 + g
    const int hy0 = min(max(ty0 - 3, 0), HW - HALO);
    const int hx0 = min(max(tx0 - 3, 0), HW - HALO);

    const float* qp = qkv + (size_t)z * PLANE;
    const float* kp = qkv + K_OFF + (size_t)z * PLANE;
    const float* vp = qkv + V_OFF + (size_t)z * PLANE;

    // Cooperative halo load: 196 pixels x 16 float4 each, for K and V.
    for (int i = threadIdx.x; i < HALO * HALO * 16; i += 256) {
        const int pl = i >> 4;
        const int f4 = (i & 15) * 4;
        const int ry = pl / HALO, rx = pl % HALO;
        const size_t gp = (size_t)((hy0 + ry) * HW + (hx0 + rx)) * 64 + f4;
        cp_async16(&kh[pl * 64 + f4], kp + gp);
        cp_async16(&vh[pl * 64 + f4], vp + gp);
    }
    cp_commit();
    cp_wait<0>();
    __syncthreads();

    const int w    = threadIdx.x >> 5;
    const int lane = threadIdx.x & 31;
    const int y    = ty0 + w;
    const int syl  = min(max(y - 3, 0), HW - KS) - hy0;   // halo-local
    const int n    = z >> 3;
    const int g    = z & 7;

    for (int px = 0; px < 8; ++px) {
        const int x   = tx0 + px;
        const int sxl = min(max(x - 3, 0), HW - KS) - hx0;

        const float2 q = *(const float2*)(qp + (size_t)(y * HW + x) * 64 + lane * 2);

        float lg[KS * KS];
#pragma unroll
        for (int a = 0; a < KS; ++a) {
            const float* krow = &kh[((syl + a) * HALO + sxl) * 64 + lane * 2];
#pragma unroll
            for (int b = 0; b < KS; ++b) {
                const float2 kv = *(const float2*)(krow + b * 64);
                float p = q.x * kv.x + q.y * kv.y;
                p += __shfl_xor_sync(0xffffffffu, p, 16);
                p += __shfl_xor_sync(0xffffffffu, p, 8);
                p += __shfl_xor_sync(0xffffffffu, p, 4);
                p += __shfl_xor_sync(0xffffffffu, p, 2);
                p += __shfl_xor_sync(0xffffffffu, p, 1);
                lg[a * KS + b] = p * 0.125f;
            }
        }

        float mx = lg[0];
#pragma unroll
        for (int j = 1; j < KS * KS; ++j) mx = fmaxf(mx, lg[j]);
        float s = 0.f;
#pragma unroll
        for (int j = 0; j < KS * KS; ++j) {
            lg[j] = __expf(lg[j] - mx);
            s += lg[j];
        }
        const float inv = 1.f / s;

        float o0 = 0.f, o1 = 0.f;
#pragma unroll
        for (int a = 0; a < KS; ++a) {
            const float* vrow = &vh[((syl + a) * HALO + sxl) * 64 + lane * 2];
#pragma unroll
            for (int b = 0; b < KS; ++b) {
                const float2 vv = *(const float2*)(vrow + b * 64);
                const float p = lg[a * KS + b];
                o0 += p * vv.x;
                o1 += p * vv.y;
            }
        }

        const size_t pix = (size_t)n * IMG_PIX + y * HW + x;
        *(float2*)(out + pix * D_MODEL + g * D_HEAD + lane * 2) =
            make_float2(o0 * inv, o1 * inv);
    }
}

// ---------------------------------------------------------------------------
extern "C" void kernel_launch(void* const* d_in, const int* in_sizes, int n_in,
                              void* d_out, int out_size) {
    const float* x     = (const float*)d_in[0];
    const float* w_qkv = (const float*)d_in[1];
    const float* w_out = (const float*)d_in[2];
    float* out = (float*)d_out;

    float* qkv = nullptr;
    float* att = nullptr;
    cudaGetSymbolAddress((void**)&qkv, g_qkv);
    cudaGetSymbolAddress((void**)&att, g_att);

    const int gemm_smem = 2 * STAGE_FLOATS * sizeof(float);  // 71680
    static bool attr_set = false;
    if (!attr_set) {
        cudaFuncSetAttribute(tgemm128<true>,  cudaFuncAttributeMaxDynamicSharedMemorySize, gemm_smem);
        cudaFuncSetAttribute(tgemm128<false>, cudaFuncAttributeMaxDynamicSharedMemorySize, gemm_smem);
        cudaFuncSetAttribute(natten2, cudaFuncAttributeMaxDynamicSharedMemorySize, (int)NATTEN_SMEM);
        attr_set = true;
    }

    // 1) QKV projection with plane-scatter epilogue
    tgemm128<true><<<dim3(QKV_N / 128, M_TOTAL / 128), 256, gemm_smem>>>(
        x, w_qkv, qkv, M_TOTAL, QKV_N, D_MODEL);

    // 2) Tiled neighborhood attention: 6x6 tiles x 16 (image,head) planes
    natten2<<<dim3(HW / 8, HW / 8, 2 * N_HEADS), 256, NATTEN_SMEM>>>(qkv, att);

    // 3) Output projection
    tgemm128<false><<<dim3(D_MODEL / 128, M_TOTAL / 128), 256, gemm_smem>>>(
        att, w_out, out, M_TOTAL, D_MODEL, D_MODEL);
}

// round 4
// speedup vs baseline: 2.5327x; 1.0432x over previous
#include <cuda_runtime.h>
#include <cstdint>

#define M_TOTAL 4608          // 2 * 48 * 48 pixels
#define D_MODEL 512
#define QKV_N   1536
#define N_HEADS 8
#define D_HEAD  64
#define KS      7
#define HW      48
#define IMG_PIX (HW * HW)     // 2304
#define PLANE   (IMG_PIX * D_HEAD)

// Scratch (device globals)
__device__ float g_qkv[M_TOTAL * QKV_N];   // q planes | k planes | v planes
__device__ float g_att[M_TOTAL * D_MODEL];

#define K_OFF ((size_t)M_TOTAL * 512)
#define V_OFF ((size_t)M_TOTAL * 1024)

// ---------------------------------------------------------------------------
__device__ __forceinline__ void cp_async16(float* smem_dst, const float* gmem_src) {
    unsigned s = (unsigned)__cvta_generic_to_shared(smem_dst);
    asm volatile("cp.async.cg.shared.global [%0], [%1], 16;" :: "r"(s), "l"(gmem_src));
}
__device__ __forceinline__ void cp_commit() { asm volatile("cp.async.commit_group;"); }
template <int N>
__device__ __forceinline__ void cp_wait() { asm volatile("cp.async.wait_group %0;" :: "n"(N)); }
__device__ __forceinline__ uint32_t f2tf32(float f) {
    uint32_t u;
    asm("cvt.rna.tf32.f32 %0, %1;" : "=r"(u) : "f"(f));
    return u;
}
__device__ __forceinline__ void mma_tf32(float c[4], const uint32_t a[4], const uint32_t b[2]) {
    asm volatile(
        "mma.sync.aligned.m16n8k8.row.col.f32.tf32.tf32.f32 "
        "{%0,%1,%2,%3}, {%4,%5,%6,%7}, {%8,%9}, {%0,%1,%2,%3};"
        : "+f"(c[0]), "+f"(c[1]), "+f"(c[2]), "+f"(c[3])
        : "r"(a[0]), "r"(a[1]), "r"(a[2]), "r"(a[3]), "r"(b[0]), "r"(b[1]));
}

// ---------------------------------------------------------------------------
// TF32 GEMM (unchanged from R3): 128x128x32, 256 threads, cp.async x2 stage.
// ---------------------------------------------------------------------------
#define A_STRIDE 36
#define B_STRIDE 136
#define STAGE_FLOATS (128 * A_STRIDE + 32 * B_STRIDE)

template <bool SCATTER>
__global__ __launch_bounds__(256, 2) void tgemm128(const float* __restrict__ A,
                                                   const float* __restrict__ B,
                                                   float* __restrict__ C,
                                                   int M, int N, int K) {
    extern __shared__ float smem[];

    const int t      = threadIdx.x;
    const int lane   = t & 31;
    const int wid    = t >> 5;
    const int warp_m = wid >> 1;
    const int warp_n = wid & 1;
    const int c_lane = lane & 3;
    const int r_lane = lane >> 2;

    const int row0 = blockIdx.y * 128;
    const int col0 = blockIdx.x * 128;
    const int NT = K / 32;

    auto load_tile = [&](int tile, int stage) {
        float* As = smem + stage * STAGE_FLOATS;
        float* Bs = As + 128 * A_STRIDE;
        const float* gA = A + (size_t)row0 * K + tile * 32;
        const float* gB = B + (size_t)(tile * 32) * N + col0;
#pragma unroll
        for (int u = 0; u < 4; ++u) {
            int i = t + u * 256;
            int arow = i >> 3, acol = (i & 7) * 4;
            cp_async16(&As[arow * A_STRIDE + acol], gA + (size_t)arow * K + acol);
        }
#pragma unroll
        for (int u = 0; u < 4; ++u) {
            int i = t + u * 256;
            int brow = i >> 5, bcol = (i & 31) * 4;
            cp_async16(&Bs[brow * B_STRIDE + bcol], gB + (size_t)brow * N + bcol);
        }
        cp_commit();
    };

    float acc[2][8][4];
#pragma unroll
    for (int mt = 0; mt < 2; ++mt)
#pragma unroll
        for (int nt = 0; nt < 8; ++nt)
#pragma unroll
            for (int j = 0; j < 4; ++j) acc[mt][nt][j] = 0.f;

    load_tile(0, 0);

    for (int tile = 0; tile < NT; ++tile) {
        const int stage = tile & 1;
        if (tile + 1 < NT) {
            load_tile(tile + 1, stage ^ 1);
            cp_wait<1>();
        } else {
            cp_wait<0>();
        }
        __syncthreads();

        const float* As = smem + stage * STAGE_FLOATS;
        const float* Bs = As + 128 * A_STRIDE;

#pragma unroll
        for (int ks = 0; ks < 4; ++ks) {
            const int kb = ks * 8;
            uint32_t af[2][4];
#pragma unroll
            for (int mt = 0; mt < 2; ++mt) {
                const int row = warp_m * 32 + mt * 16 + r_lane;
                af[mt][0] = f2tf32(As[row * A_STRIDE + kb + c_lane]);
                af[mt][1] = f2tf32(As[(row + 8) * A_STRIDE + kb + c_lane]);
                af[mt][2] = f2tf32(As[row * A_STRIDE + kb + 4 + c_lane]);
                af[mt][3] = f2tf32(As[(row + 8) * A_STRIDE + kb + 4 + c_lane]);
            }
            uint32_t bf[8][2];
#pragma unroll
            for (int nt = 0; nt < 8; ++nt) {
                const int col = warp_n * 64 + nt * 8 + r_lane;
                bf[nt][0] = f2tf32(Bs[(kb + c_lane) * B_STRIDE + col]);
                bf[nt][1] = f2tf32(Bs[(kb + 4 + c_lane) * B_STRIDE + col]);
            }
#pragma unroll
            for (int mt = 0; mt < 2; ++mt)
#pragma unroll
                for (int nt = 0; nt < 8; ++nt)
                    mma_tf32(acc[mt][nt], af[mt], bf[nt]);
        }
        __syncthreads();
    }

    const int img_n = row0 >= IMG_PIX;
#pragma unroll
    for (int mt = 0; mt < 2; ++mt) {
        const int row_g = row0 + warp_m * 32 + mt * 16 + r_lane;
#pragma unroll
        for (int nt = 0; nt < 8; ++nt) {
            const int col_g = col0 + warp_n * 64 + nt * 8 + 2 * c_lane;
            if (!SCATTER) {
                *(float2*)&C[(size_t)row_g * N + col_g] =
                    make_float2(acc[mt][nt][0], acc[mt][nt][1]);
                *(float2*)&C[(size_t)(row_g + 8) * N + col_g] =
                    make_float2(acc[mt][nt][2], acc[mt][nt][3]);
            } else {
                const int which = col_g >> 9;
                const int g     = (col_g >> 6) & 7;
                const int e     = col_g & 63;
                const int p     = row_g - img_n * IMG_PIX;
                float* dst = C + (size_t)which * K_OFF +
                             ((size_t)(img_n * 8 + g) * IMG_PIX + p) * 64 + e;
                *(float2*)dst = make_float2(acc[mt][nt][0], acc[mt][nt][1]);
                *(float2*)(dst + 8 * 64) = make_float2(acc[mt][nt][2], acc[mt][nt][3]);
            }
        }
    }
}

// ---------------------------------------------------------------------------
// natten3: lane-per-neighbor attention. Block = 8x4 pixel tile, one (img,head).
// Halo 14x10 K (stride 68) + V (stride 64) + Q tile + per-warp p[] in smem.
// Warp w handles tile row w (4 pixels). Lane j owns neighbors j and j+32.
// ---------------------------------------------------------------------------
#define TY 8
#define TX 4
#define HY 14
#define HX 10
#define HP (HY * HX)              // 140
#define KSTR 68
#define NAT_SMEM ((HP * KSTR + HP * 64 + TY * TX * 64 + 8 * 64) * sizeof(float))

__global__ __launch_bounds__(256, 2) void natten3(const float* __restrict__ qkv,
                                                  float* __restrict__ out) {
    extern __shared__ float sh[];
    float* kh = sh;                        // [140][68]
    float* vh = kh + HP * KSTR;            // [140][64]
    float* qs = vh + HP * 64;              // [32][64]
    float* ps = qs + TY * TX * 64;         // [8][64]

    const int tx0 = blockIdx.x * TX;
    const int ty0 = blockIdx.y * TY;
    const int z   = blockIdx.z;            // n*8 + g
    const int hy0 = min(max(ty0 - 3, 0), HW - HY);
    const int hx0 = min(max(tx0 - 3, 0), HW - HX);

    const float* qp = qkv + (size_t)z * PLANE;
    const float* kp = qkv + K_OFF + (size_t)z * PLANE;
    const float* vp = qkv + V_OFF + (size_t)z * PLANE;

    // Cooperative halo + q loads
    for (int i = threadIdx.x; i < HP * 16; i += 256) {
        const int pl = i >> 4, f4 = (i & 15) * 4;
        const int ry = pl / HX, rx = pl % HX;
        const size_t gp = (size_t)((hy0 + ry) * HW + hx0 + rx) * 64 + f4;
        cp_async16(&kh[pl * KSTR + f4], kp + gp);
        cp_async16(&vh[pl * 64 + f4], vp + gp);
    }
    for (int i = threadIdx.x; i < TY * TX * 16; i += 256) {
        const int pl = i >> 4, f4 = (i & 15) * 4;
        const int py = pl >> 2, px = pl & 3;
        const size_t gp = (size_t)((ty0 + py) * HW + tx0 + px) * 64 + f4;
        cp_async16(&qs[pl * 64 + f4], qp + gp);
    }
    cp_commit();
    cp_wait<0>();
    __syncthreads();

    const int w    = threadIdx.x >> 5;
    const int lane = threadIdx.x & 31;
    const int y    = ty0 + w;
    const int syl  = min(max(y - 3, 0), HW - KS) - hy0;
    const int n    = z >> 3;
    const int g    = z & 7;

    // lane -> neighbor mapping
    const int a0 = lane / 7, b0 = lane % 7;
    const int j1 = lane + 32;
    const bool has1 = (j1 < KS * KS);
    const int a1 = has1 ? j1 / 7 : a0;
    const int b1 = has1 ? j1 % 7 : b0;
    const int base0 = (syl + a0) * HX + b0;
    const int base1 = (syl + a1) * HX + b1;

    float* pw = ps + w * 64;

    for (int px = 0; px < TX; ++px) {
        const int x   = tx0 + px;
        const int sxl = min(max(x - 3, 0), HW - KS) - hx0;

        const float4* q4  = (const float4*)(qs + (w * TX + px) * 64);
        const float4* k0p = (const float4*)(kh + (base0 + sxl) * KSTR);
        const float4* k1p = (const float4*)(kh + (base1 + sxl) * KSTR);

        float acc0 = 0.f, acc1 = 0.f;
#pragma unroll
        for (int d = 0; d < 16; ++d) {
            const float4 q  = q4[d];
            const float4 k0 = k0p[d];
            const float4 k1 = k1p[d];
            acc0 += q.x * k0.x + q.y * k0.y + q.z * k0.z + q.w * k0.w;
            acc1 += q.x * k1.x + q.y * k1.y + q.z * k1.z + q.w * k1.w;
        }

        const float l0 = acc0 * 0.125f;
        const float l1 = has1 ? acc1 * 0.125f : -1e30f;
        float m = fmaxf(l0, l1);
#pragma unroll
        for (int o = 16; o; o >>= 1) m = fmaxf(m, __shfl_xor_sync(0xffffffffu, m, o));
        const float e0 = __expf(l0 - m);
        const float e1 = has1 ? __expf(l1 - m) : 0.f;
        float s = e0 + e1;
#pragma unroll
        for (int o = 16; o; o >>= 1) s += __shfl_xor_sync(0xffffffffu, s, o);
        const float inv = 1.f / s;

        pw[lane] = e0;
        if (has1) pw[j1] = e1;
        __syncwarp();

        float o0 = 0.f, o1 = 0.f;
#pragma unroll
        for (int a = 0; a < KS; ++a) {
            const float* vr = vh + ((syl + a) * HX + sxl) * 64 + lane * 2;
            const float* pr = pw + a * KS;
#pragma unroll
            for (int b = 0; b < KS; ++b) {
                const float p = pr[b];
                const float2 v2 = *(const float2*)(vr + b * 64);
                o0 += p * v2.x;
                o1 += p * v2.y;
            }
        }

        const size_t pix = (size_t)n * IMG_PIX + y * HW + x;
        *(float2*)(out + pix * D_MODEL + g * D_HEAD + lane * 2) =
            make_float2(o0 * inv, o1 * inv);
        __syncwarp();   // protect pw before next pixel overwrites it
    }
}

// ---------------------------------------------------------------------------
extern "C" void kernel_launch(void* const* d_in, const int* in_sizes, int n_in,
                              void* d_out, int out_size) {
    const float* x     = (const float*)d_in[0];
    const float* w_qkv = (const float*)d_in[1];
    const float* w_out = (const float*)d_in[2];
    float* out = (float*)d_out;

    float* qkv = nullptr;
    float* att = nullptr;
    cudaGetSymbolAddress((void**)&qkv, g_qkv);
    cudaGetSymbolAddress((void**)&att, g_att);

    const int gemm_smem = 2 * STAGE_FLOATS * sizeof(float);
    static bool attr_set = false;
    if (!attr_set) {
        cudaFuncSetAttribute(tgemm128<true>,  cudaFuncAttributeMaxDynamicSharedMemorySize, gemm_smem);
        cudaFuncSetAttribute(tgemm128<false>, cudaFuncAttributeMaxDynamicSharedMemorySize, gemm_smem);
        cudaFuncSetAttribute(natten3, cudaFuncAttributeMaxDynamicSharedMemorySize, (int)NAT_SMEM);
        attr_set = true;
    }

    // 1) QKV projection with plane-scatter epilogue
    tgemm128<true><<<dim3(QKV_N / 128, M_TOTAL / 128), 256, gemm_smem>>>(
        x, w_qkv, qkv, M_TOTAL, QKV_N, D_MODEL);

    // 2) Lane-per-neighbor attention: 12x6 tiles x 16 (image,head) planes
    natten3<<<dim3(HW / TX, HW / TY, 2 * N_HEADS), 256, NAT_SMEM>>>(qkv, att);

    // 3) Output projection
    tgemm128<false><<<dim3(D_MODEL / 128, M_TOTAL / 128), 256, gemm_smem>>>(
        att, w_out, out, M_TOTAL, D_MODEL, D_MODEL);
}

// round 5
// speedup vs baseline: 4.1364x; 1.6332x over previous
#include <cuda_runtime.h>
#include <cuda_fp16.h>
#include <cstdint>

#define M_TOTAL 4608          // 2 * 48 * 48 pixels
#define D_MODEL 512
#define QKV_N   1536
#define N_HEADS 8
#define D_HEAD  64
#define KS      7
#define HW      48
#define IMG_PIX (HW * HW)     // 2304
#define PLANE   (IMG_PIX * D_HEAD)

// fp16 scratch (device globals)
__device__ __half g_xh[M_TOTAL * D_MODEL];
__device__ __half g_wqkvh[D_MODEL * QKV_N];
__device__ __half g_wouth[D_MODEL * D_MODEL];
__device__ __half g_qkvh[M_TOTAL * QKV_N];   // q planes | k planes | v planes
__device__ __half g_atth[M_TOTAL * D_MODEL];

#define K_OFF ((size_t)M_TOTAL * 512)
#define V_OFF ((size_t)M_TOTAL * 1024)

// ---------------------------------------------------------------------------
__device__ __forceinline__ void cp_async16(void* smem_dst, const void* gmem_src) {
    unsigned s = (unsigned)__cvta_generic_to_shared(smem_dst);
    asm volatile("cp.async.cg.shared.global [%0], [%1], 16;" :: "r"(s), "l"(gmem_src));
}
__device__ __forceinline__ void cp_async8(void* smem_dst, const void* gmem_src) {
    unsigned s = (unsigned)__cvta_generic_to_shared(smem_dst);
    asm volatile("cp.async.ca.shared.global [%0], [%1], 8;" :: "r"(s), "l"(gmem_src));
}
__device__ __forceinline__ void cp_commit() { asm volatile("cp.async.commit_group;"); }
template <int N>
__device__ __forceinline__ void cp_wait() { asm volatile("cp.async.wait_group %0;" :: "n"(N)); }

__device__ __forceinline__ void ldsm_x4(uint32_t r[4], const __half* p) {
    uint32_t a = (uint32_t)__cvta_generic_to_shared(p);
    asm volatile("ldmatrix.sync.aligned.m8n8.x4.shared.b16 {%0,%1,%2,%3}, [%4];"
                 : "=r"(r[0]), "=r"(r[1]), "=r"(r[2]), "=r"(r[3]) : "r"(a));
}
__device__ __forceinline__ void ldsm_x4t(uint32_t r[4], const __half* p) {
    uint32_t a = (uint32_t)__cvta_generic_to_shared(p);
    asm volatile("ldmatrix.sync.aligned.m8n8.x4.trans.shared.b16 {%0,%1,%2,%3}, [%4];"
                 : "=r"(r[0]), "=r"(r[1]), "=r"(r[2]), "=r"(r[3]) : "r"(a));
}
__device__ __forceinline__ void mma16816(float c[4], const uint32_t a[4], const uint32_t* b) {
    asm volatile(
        "mma.sync.aligned.m16n8k16.row.col.f32.f16.f16.f32 "
        "{%0,%1,%2,%3}, {%4,%5,%6,%7}, {%8,%9}, {%0,%1,%2,%3};"
        : "+f"(c[0]), "+f"(c[1]), "+f"(c[2]), "+f"(c[3])
        : "r"(a[0]), "r"(a[1]), "r"(a[2]), "r"(a[3]), "r"(b[0]), "r"(b[1]));
}

// ---------------------------------------------------------------------------
// Fused f32 -> f16 conversion for three arrays (float4 granularity).
// ---------------------------------------------------------------------------
__global__ void cvt3(const float* __restrict__ s0, __half* __restrict__ d0, int n0,
                     const float* __restrict__ s1, __half* __restrict__ d1, int n1,
                     const float* __restrict__ s2, __half* __restrict__ d2, int n2) {
    int i = blockIdx.x * blockDim.x + threadIdx.x;
    const int t0 = n0 >> 2, t1 = t0 + (n1 >> 2), t2 = t1 + (n2 >> 2);
    const float* s; __half* d; int j;
    if (i < t0)      { s = s0; d = d0; j = i; }
    else if (i < t1) { s = s1; d = d1; j = i - t0; }
    else if (i < t2) { s = s2; d = d2; j = i - t1; }
    else return;
    float4 v = ((const float4*)s)[j];
    ((__half2*)d)[j * 2]     = __floats2half2_rn(v.x, v.y);
    ((__half2*)d)[j * 2 + 1] = __floats2half2_rn(v.z, v.w);
}

// ---------------------------------------------------------------------------
// fp16 tensor-core GEMM: C[M,N] = A[M,K] @ B[K,N], A/B fp16 row-major.
// Block tile 128x128x32, 256 threads (8 warps = 4m x 2n), warp tile 32x64.
// mma.m16n8k16 via ldmatrix. Double-buffered cp.async.
// SCATTER: C = fp16 q/k/v planes; else C = fp32 row-major.
// ---------------------------------------------------------------------------
#define HA_STR 40     // halves: 32 data + 8 pad (80B row -> ldmatrix conflict-free)
#define HB_STR 136    // halves: 128 data + 8 pad (272B row)
#define HSTAGE (128 * HA_STR + 32 * HB_STR)   // 9472 halves

template <bool SCATTER>
__global__ __launch_bounds__(256, 2) void hgemm(const __half* __restrict__ A,
                                                const __half* __restrict__ B,
                                                void* __restrict__ Cv,
                                                int M, int N, int K) {
    extern __shared__ __half hsm[];

    const int t      = threadIdx.x;
    const int lane   = t & 31;
    const int wid    = t >> 5;
    const int warp_m = wid >> 1;
    const int warp_n = wid & 1;
    const int c_lane = lane & 3;
    const int r_lane = lane >> 2;

    const int row0 = blockIdx.y * 128;
    const int col0 = blockIdx.x * 128;
    const int NT = K / 32;

    auto load_tile = [&](int tile, int stage) {
        __half* As = hsm + stage * HSTAGE;
        __half* Bs = As + 128 * HA_STR;
        const __half* gA = A + (size_t)row0 * K + tile * 32;
        const __half* gB = B + (size_t)(tile * 32) * N + col0;
#pragma unroll
        for (int u = 0; u < 2; ++u) {
            int i = t + u * 256;                       // 512 chunks: 128 rows x 4
            int arow = i >> 2, acol = (i & 3) * 8;
            cp_async16(&As[arow * HA_STR + acol], gA + (size_t)arow * K + acol);
        }
#pragma unroll
        for (int u = 0; u < 2; ++u) {
            int i = t + u * 256;                       // 512 chunks: 32 rows x 16
            int brow = i >> 4, bcol = (i & 15) * 8;
            cp_async16(&Bs[brow * HB_STR + bcol], gB + (size_t)brow * N + bcol);
        }
        cp_commit();
    };

    float acc[2][8][4];
#pragma unroll
    for (int mt = 0; mt < 2; ++mt)
#pragma unroll
        for (int nt = 0; nt < 8; ++nt)
#pragma unroll
            for (int j = 0; j < 4; ++j) acc[mt][nt][j] = 0.f;

    load_tile(0, 0);

    for (int tile = 0; tile < NT; ++tile) {
        const int stage = tile & 1;
        if (tile + 1 < NT) {
            load_tile(tile + 1, stage ^ 1);
            cp_wait<1>();
        } else {
            cp_wait<0>();
        }
        __syncthreads();

        const __half* As = hsm + stage * HSTAGE;
        const __half* Bs = As + 128 * HA_STR;

#pragma unroll
        for (int ks = 0; ks < 2; ++ks) {
            const int k0 = ks * 16;
            // A fragments: m16k16 tiles (rows 0-15: lane&15; k-half: lane>>4)
            uint32_t af[2][4];
            const __half* ap = As + (warp_m * 32 + (lane & 15)) * HA_STR
                                  + k0 + ((lane >> 4) << 3);
            ldsm_x4(af[0], ap);
            ldsm_x4(af[1], ap + 16 * HA_STR);
            // B fragments: k16n16 tiles via x4.trans (4 tiles cover n=64)
            uint32_t bf[4][4];
            const __half* bp = Bs + (k0 + ((lane >> 3) & 1) * 8 + (lane & 7)) * HB_STR
                                  + warp_n * 64 + (lane >> 4) * 8;
#pragma unroll
            for (int nb = 0; nb < 4; ++nb)
                ldsm_x4t(bf[nb], bp + nb * 16);
#pragma unroll
            for (int mt = 0; mt < 2; ++mt)
#pragma unroll
                for (int nt = 0; nt < 8; ++nt)
                    mma16816(acc[mt][nt], af[mt], &bf[nt >> 1][(nt & 1) * 2]);
        }
        __syncthreads();
    }

    const int img_n = row0 >= IMG_PIX;
#pragma unroll
    for (int mt = 0; mt < 2; ++mt) {
        const int row_g = row0 + warp_m * 32 + mt * 16 + r_lane;
#pragma unroll
        for (int nt = 0; nt < 8; ++nt) {
            const int col_g = col0 + warp_n * 64 + nt * 8 + 2 * c_lane;
            if (!SCATTER) {
                float* C = (float*)Cv;
                *(float2*)&C[(size_t)row_g * N + col_g] =
                    make_float2(acc[mt][nt][0], acc[mt][nt][1]);
                *(float2*)&C[(size_t)(row_g + 8) * N + col_g] =
                    make_float2(acc[mt][nt][2], acc[mt][nt][3]);
            } else {
                __half* C = (__half*)Cv;
                const int which = col_g >> 9;
                const int g     = (col_g >> 6) & 7;
                const int e     = col_g & 63;
                const int p     = row_g - img_n * IMG_PIX;
                __half* dst = C + (size_t)which * K_OFF +
                              ((size_t)(img_n * 8 + g) * IMG_PIX + p) * 64 + e;
                *(__half2*)dst = __floats2half2_rn(acc[mt][nt][0], acc[mt][nt][1]);
                *(__half2*)(dst + 8 * 64) = __floats2half2_rn(acc[mt][nt][2], acc[mt][nt][3]);
            }
        }
    }
}

// ---------------------------------------------------------------------------
// natten4: lane-per-neighbor attention on fp16 planes.
// Block = 8x4 pixel tile, one (img,head). Halo 14x10 K/V + Q in fp16 smem.
// ---------------------------------------------------------------------------
#define TY 8
#define TX 4
#define HY 14
#define HX 10
#define HP (HY * HX)          // 140
#define KSTR 68               // halves (136B row, 8B aligned)
#define NAT_SMEM ((HP * KSTR + HP * 64 + TY * TX * 64) * sizeof(__half) \
                  + 8 * 64 * sizeof(float))

__device__ __forceinline__ float2 h2f(uint32_t u) {
    return __half22float2(*(__half2*)&u);
}

__global__ __launch_bounds__(256) void natten4(const __half* __restrict__ qkv,
                                               __half* __restrict__ out) {
    extern __shared__ __half shh[];
    __half* kh = shh;                      // [140][68]
    __half* vh = kh + HP * KSTR;           // [140][64]
    __half* qs = vh + HP * 64;             // [32][64]
    float*  ps = (float*)(qs + TY * TX * 64);   // [8][64]

    const int tx0 = blockIdx.x * TX;
    const int ty0 = blockIdx.y * TY;
    const int z   = blockIdx.z;            // n*8 + g
    const int hy0 = min(max(ty0 - 3, 0), HW - HY);
    const int hx0 = min(max(tx0 - 3, 0), HW - HX);

    const __half* qp = qkv + (size_t)z * PLANE;
    const __half* kp = qkv + K_OFF + (size_t)z * PLANE;
    const __half* vp = qkv + V_OFF + (size_t)z * PLANE;

    // K halo: 140 rows x 16 chunks of 8B (KSTR stride only 8B-aligned)
    for (int i = threadIdx.x; i < HP * 16; i += 256) {
        const int pl = i >> 4, c = i & 15;
        const int ry = pl / HX, rx = pl % HX;
        const size_t gp = (size_t)((hy0 + ry) * HW + hx0 + rx) * 64 + c * 4;
        cp_async8(&kh[pl * KSTR + c * 4], kp + gp);
    }
    // V halo: 140 rows x 8 chunks of 16B
    for (int i = threadIdx.x; i < HP * 8; i += 256) {
        const int pl = i >> 3, c = i & 7;
        const int ry = pl / HX, rx = pl % HX;
        const size_t gp = (size_t)((hy0 + ry) * HW + hx0 + rx) * 64 + c * 8;
        cp_async16(&vh[pl * 64 + c * 8], vp + gp);
    }
    // Q tile: 32 pixels x 8 chunks of 16B
    for (int i = threadIdx.x; i < TY * TX * 8; i += 256) {
        const int pl = i >> 3, c = i & 7;
        const int py = pl >> 2, px = pl & 3;
        const size_t gp = (size_t)((ty0 + py) * HW + tx0 + px) * 64 + c * 8;
        cp_async16(&qs[pl * 64 + c * 8], qp + gp);
    }
    cp_commit();
    cp_wait<0>();
    __syncthreads();

    const int w    = threadIdx.x >> 5;
    const int lane = threadIdx.x & 31;
    const int y    = ty0 + w;
    const int syl  = min(max(y - 3, 0), HW - KS) - hy0;
    const int n    = z >> 3;
    const int g    = z & 7;

    const int a0 = lane / 7, b0 = lane % 7;
    const int j1 = lane + 32;
    const bool has1 = (j1 < KS * KS);
    const int a1 = has1 ? j1 / 7 : a0;
    const int b1 = has1 ? j1 % 7 : b0;
    const int base0 = (syl + a0) * HX + b0;
    const int base1 = (syl + a1) * HX + b1;

    float* pw = ps + w * 64;

    for (int px = 0; px < TX; ++px) {
        const int x   = tx0 + px;
        const int sxl = min(max(x - 3, 0), HW - KS) - hx0;

        const uint2* q2  = (const uint2*)(qs + (w * TX + px) * 64);
        const uint2* k0p = (const uint2*)(kh + (base0 + sxl) * KSTR);
        const uint2* k1p = (const uint2*)(kh + (base1 + sxl) * KSTR);

        float acc0 = 0.f, acc1 = 0.f;
#pragma unroll
        for (int d = 0; d < 16; ++d) {
            const uint2 qd = q2[d];
            const uint2 ka = k0p[d];
            const uint2 kb = k1p[d];
            const float2 qx = h2f(qd.x), qy = h2f(qd.y);
            const float2 ax = h2f(ka.x), ay = h2f(ka.y);
            const float2 bx = h2f(kb.x), by = h2f(kb.y);
            acc0 += qx.x * ax.x + qx.y * ax.y + qy.x * ay.x + qy.y * ay.y;
            acc1 += qx.x * bx.x + qx.y * bx.y + qy.x * by.x + qy.y * by.y;
        }

        const float l0 = acc0 * 0.125f;
        const float l1 = has1 ? acc1 * 0.125f : -1e30f;
        float m = fmaxf(l0, l1);
#pragma unroll
        for (int o = 16; o; o >>= 1) m = fmaxf(m, __shfl_xor_sync(0xffffffffu, m, o));
        const float e0 = __expf(l0 - m);
        const float e1 = has1 ? __expf(l1 - m) : 0.f;
        float s = e0 + e1;
#pragma unroll
        for (int o = 16; o; o >>= 1) s += __shfl_xor_sync(0xffffffffu, s, o);
        const float inv = 1.f / s;

        pw[lane] = e0;
        if (has1) pw[j1] = e1;
        __syncwarp();

        float o0 = 0.f, o1 = 0.f;
#pragma unroll
        for (int a = 0; a < KS; ++a) {
            const __half* vr = vh + ((syl + a) * HX + sxl) * 64 + lane * 2;
            const float* pr = pw + a * KS;
#pragma unroll
            for (int b = 0; b < KS; ++b) {
                const float p = pr[b];
                const float2 v2 = __half22float2(*(const __half2*)(vr + b * 64));
                o0 += p * v2.x;
                o1 += p * v2.y;
            }
        }

        const size_t pix = (size_t)n * IMG_PIX + y * HW + x;
        *(__half2*)(out + pix * D_MODEL + g * D_HEAD + lane * 2) =
            __floats2half2_rn(o0 * inv, o1 * inv);
        __syncwarp();   // protect pw before next pixel overwrites it
    }
}

// ---------------------------------------------------------------------------
extern "C" void kernel_launch(void* const* d_in, const int* in_sizes, int n_in,
                              void* d_out, int out_size) {
    const float* x     = (const float*)d_in[0];
    const float* w_qkv = (const float*)d_in[1];
    const float* w_out = (const float*)d_in[2];
    float* out = (float*)d_out;

    __half *xh, *wqkvh, *wouth, *qkvh, *atth;
    cudaGetSymbolAddress((void**)&xh, g_xh);
    cudaGetSymbolAddress((void**)&wqkvh, g_wqkvh);
    cudaGetSymbolAddress((void**)&wouth, g_wouth);
    cudaGetSymbolAddress((void**)&qkvh, g_qkvh);
    cudaGetSymbolAddress((void**)&atth, g_atth);

    const int hsmem = 2 * HSTAGE * sizeof(__half);   // 37888
    static bool attr_set = false;
    if (!attr_set) {
        cudaFuncSetAttribute(hgemm<true>,  cudaFuncAttributeMaxDynamicSharedMemorySize, hsmem);
        cudaFuncSetAttribute(hgemm<false>, cudaFuncAttributeMaxDynamicSharedMemorySize, hsmem);
        cudaFuncSetAttribute(natten4, cudaFuncAttributeMaxDynamicSharedMemorySize, (int)NAT_SMEM);
        attr_set = true;
    }

    // 0) Convert x, w_qkv, w_out to fp16
    const int NX = M_TOTAL * D_MODEL, NWQ = D_MODEL * QKV_N, NWO = D_MODEL * D_MODEL;
    const int tot4 = (NX + NWQ + NWO) / 4;
    cvt3<<<(tot4 + 255) / 256, 256>>>(x, xh, NX, w_qkv, wqkvh, NWQ, w_out, wouth, NWO);

    // 1) QKV projection (fp16 mma) with plane-scatter epilogue
    hgemm<true><<<dim3(QKV_N / 128, M_TOTAL / 128), 256, hsmem>>>(
        xh, wqkvh, qkvh, M_TOTAL, QKV_N, D_MODEL);

    // 2) Lane-per-neighbor attention on fp16 planes
    natten4<<<dim3(HW / TX, HW / TY, 2 * N_HEADS), 256, NAT_SMEM>>>(qkvh, atth);

    // 3) Output projection (fp16 mma) -> fp32 output
    hgemm<false><<<dim3(D_MODEL / 128, M_TOTAL / 128), 256, hsmem>>>(
        atth, wouth, out, M_TOTAL, D_MODEL, D_MODEL);
}

// round 6
// speedup vs baseline: 5.6413x; 1.3638x over previous
#include <cuda_runtime.h>
#include <cuda_fp16.h>
#include <cstdint>

#define M_TOTAL 4608          // 2 * 48 * 48 pixels
#define D_MODEL 512
#define QKV_N   1536
#define N_HEADS 8
#define D_HEAD  64
#define KS      7
#define HW      48
#define IMG_PIX (HW * HW)     // 2304
#define PLANE   (IMG_PIX * D_HEAD)

// fp16 scratch (device globals)
__device__ __half g_xh[M_TOTAL * D_MODEL];
__device__ __half g_wqkvh[D_MODEL * QKV_N];
__device__ __half g_wouth[D_MODEL * D_MODEL];
__device__ __half g_qkvh[M_TOTAL * QKV_N];   // q planes | k planes | v planes
__device__ __half g_atth[M_TOTAL * D_MODEL];

#define K_OFF ((size_t)M_TOTAL * 512)
#define V_OFF ((size_t)M_TOTAL * 1024)

// ---------------------------------------------------------------------------
__device__ __forceinline__ void cp_async16(void* smem_dst, const void* gmem_src) {
    unsigned s = (unsigned)__cvta_generic_to_shared(smem_dst);
    asm volatile("cp.async.cg.shared.global [%0], [%1], 16;" :: "r"(s), "l"(gmem_src));
}
__device__ __forceinline__ void cp_commit() { asm volatile("cp.async.commit_group;"); }
template <int N>
__device__ __forceinline__ void cp_wait() { asm volatile("cp.async.wait_group %0;" :: "n"(N)); }

__device__ __forceinline__ void ldsm_x4(uint32_t r[4], const __half* p) {
    uint32_t a = (uint32_t)__cvta_generic_to_shared(p);
    asm volatile("ldmatrix.sync.aligned.m8n8.x4.shared.b16 {%0,%1,%2,%3}, [%4];"
                 : "=r"(r[0]), "=r"(r[1]), "=r"(r[2]), "=r"(r[3]) : "r"(a));
}
__device__ __forceinline__ void ldsm_x4t(uint32_t r[4], const __half* p) {
    uint32_t a = (uint32_t)__cvta_generic_to_shared(p);
    asm volatile("ldmatrix.sync.aligned.m8n8.x4.trans.shared.b16 {%0,%1,%2,%3}, [%4];"
                 : "=r"(r[0]), "=r"(r[1]), "=r"(r[2]), "=r"(r[3]) : "r"(a));
}
__device__ __forceinline__ void mma16816(float c[4], const uint32_t a[4],
                                         uint32_t b0, uint32_t b1) {
    asm volatile(
        "mma.sync.aligned.m16n8k16.row.col.f32.f16.f16.f32 "
        "{%0,%1,%2,%3}, {%4,%5,%6,%7}, {%8,%9}, {%0,%1,%2,%3};"
        : "+f"(c[0]), "+f"(c[1]), "+f"(c[2]), "+f"(c[3])
        : "r"(a[0]), "r"(a[1]), "r"(a[2]), "r"(a[3]), "r"(b0), "r"(b1));
}

// ---------------------------------------------------------------------------
// Fused f32 -> f16 conversion for three arrays.
// ---------------------------------------------------------------------------
__global__ void cvt3(const float* __restrict__ s0, __half* __restrict__ d0, int n0,
                     const float* __restrict__ s1, __half* __restrict__ d1, int n1,
                     const float* __restrict__ s2, __half* __restrict__ d2, int n2) {
    int i = blockIdx.x * blockDim.x + threadIdx.x;
    const int t0 = n0 >> 2, t1 = t0 + (n1 >> 2), t2 = t1 + (n2 >> 2);
    const float* s; __half* d; int j;
    if (i < t0)      { s = s0; d = d0; j = i; }
    else if (i < t1) { s = s1; d = d1; j = i - t0; }
    else if (i < t2) { s = s2; d = d2; j = i - t1; }
    else return;
    float4 v = ((const float4*)s)[j];
    ((__half2*)d)[j * 2]     = __floats2half2_rn(v.x, v.y);
    ((__half2*)d)[j * 2 + 1] = __floats2half2_rn(v.z, v.w);
}

// ---------------------------------------------------------------------------
// fp16 GEMM (unchanged from R5): 128x128x32, mma.m16n8k16 + ldmatrix.
// ---------------------------------------------------------------------------
#define HA_STR 40
#define HB_STR 136
#define HSTAGE (128 * HA_STR + 32 * HB_STR)

template <bool SCATTER>
__global__ __launch_bounds__(256, 2) void hgemm(const __half* __restrict__ A,
                                                const __half* __restrict__ B,
                                                void* __restrict__ Cv,
                                                int M, int N, int K) {
    extern __shared__ __half hsm[];

    const int t      = threadIdx.x;
    const int lane   = t & 31;
    const int wid    = t >> 5;
    const int warp_m = wid >> 1;
    const int warp_n = wid & 1;
    const int c_lane = lane & 3;
    const int r_lane = lane >> 2;

    const int row0 = blockIdx.y * 128;
    const int col0 = blockIdx.x * 128;
    const int NT = K / 32;

    auto load_tile = [&](int tile, int stage) {
        __half* As = hsm + stage * HSTAGE;
        __half* Bs = As + 128 * HA_STR;
        const __half* gA = A + (size_t)row0 * K + tile * 32;
        const __half* gB = B + (size_t)(tile * 32) * N + col0;
#pragma unroll
        for (int u = 0; u < 2; ++u) {
            int i = t + u * 256;
            int arow = i >> 2, acol = (i & 3) * 8;
            cp_async16(&As[arow * HA_STR + acol], gA + (size_t)arow * K + acol);
        }
#pragma unroll
        for (int u = 0; u < 2; ++u) {
            int i = t + u * 256;
            int brow = i >> 4, bcol = (i & 15) * 8;
            cp_async16(&Bs[brow * HB_STR + bcol], gB + (size_t)brow * N + bcol);
        }
        cp_commit();
    };

    float acc[2][8][4];
#pragma unroll
    for (int mt = 0; mt < 2; ++mt)
#pragma unroll
        for (int nt = 0; nt < 8; ++nt)
#pragma unroll
            for (int j = 0; j < 4; ++j) acc[mt][nt][j] = 0.f;

    load_tile(0, 0);

    for (int tile = 0; tile < NT; ++tile) {
        const int stage = tile & 1;
        if (tile + 1 < NT) {
            load_tile(tile + 1, stage ^ 1);
            cp_wait<1>();
        } else {
            cp_wait<0>();
        }
        __syncthreads();

        const __half* As = hsm + stage * HSTAGE;
        const __half* Bs = As + 128 * HA_STR;

#pragma unroll
        for (int ks = 0; ks < 2; ++ks) {
            const int k0 = ks * 16;
            uint32_t af[2][4];
            const __half* ap = As + (warp_m * 32 + (lane & 15)) * HA_STR
                                  + k0 + ((lane >> 4) << 3);
            ldsm_x4(af[0], ap);
            ldsm_x4(af[1], ap + 16 * HA_STR);
            uint32_t bf[4][4];
            const __half* bp = Bs + (k0 + ((lane >> 3) & 1) * 8 + (lane & 7)) * HB_STR
                                  + warp_n * 64 + (lane >> 4) * 8;
#pragma unroll
            for (int nb = 0; nb < 4; ++nb)
                ldsm_x4t(bf[nb], bp + nb * 16);
#pragma unroll
            for (int mt = 0; mt < 2; ++mt)
#pragma unroll
                for (int nt = 0; nt < 8; ++nt)
                    mma16816(acc[mt][nt], af[mt],
                             bf[nt >> 1][(nt & 1) * 2], bf[nt >> 1][(nt & 1) * 2 + 1]);
        }
        __syncthreads();
    }

    const int img_n = row0 >= IMG_PIX;
#pragma unroll
    for (int mt = 0; mt < 2; ++mt) {
        const int row_g = row0 + warp_m * 32 + mt * 16 + r_lane;
#pragma unroll
        for (int nt = 0; nt < 8; ++nt) {
            const int col_g = col0 + warp_n * 64 + nt * 8 + 2 * c_lane;
            if (!SCATTER) {
                float* C = (float*)Cv;
                *(float2*)&C[(size_t)row_g * N + col_g] =
                    make_float2(acc[mt][nt][0], acc[mt][nt][1]);
                *(float2*)&C[(size_t)(row_g + 8) * N + col_g] =
                    make_float2(acc[mt][nt][2], acc[mt][nt][3]);
            } else {
                __half* C = (__half*)Cv;
                const int which = col_g >> 9;
                const int g     = (col_g >> 6) & 7;
                const int e     = col_g & 63;
                const int p     = row_g - img_n * IMG_PIX;
                __half* dst = C + (size_t)which * K_OFF +
                              ((size_t)(img_n * 8 + g) * IMG_PIX + p) * 64 + e;
                *(__half2*)dst = __floats2half2_rn(acc[mt][nt][0], acc[mt][nt][1]);
                *(__half2*)(dst + 8 * 64) = __floats2half2_rn(acc[mt][nt][2], acc[mt][nt][3]);
            }
        }
    }
}

// ---------------------------------------------------------------------------
// natten5: dense masked attention on tensor cores.
// Block = 8x8 queries (64), one (img,head). Halo 14x14 padded to 14x16 = 224.
// S = Q(64x64)·K^T(224x64), mask, softmax, P fp16 -> smem,
// O = P(64x224)·V(224x64). 8 warps = 4 m-tiles x 2 n-halves.
// ---------------------------------------------------------------------------
#define HN   224              // padded halo positions (14 x 16)
#define HSTR 72               // K/V/Q smem stride in halves
#define PSTR 232              // P smem stride in halves
#define NAT5_SMEM ((2 * HN * HSTR + 64 * HSTR + 64 * PSTR) * sizeof(__half) \
                   + 4 * 64 * sizeof(float))

__global__ __launch_bounds__(256) void natten5(const __half* __restrict__ qkv,
                                               __half* __restrict__ out) {
    extern __shared__ __half shh[];
    __half* Kh = shh;                       // [224][72]
    __half* Vh = Kh + HN * HSTR;            // [224][72]
    __half* Qs = Vh + HN * HSTR;            // [64][72]
    __half* Ps = Qs + 64 * HSTR;            // [64][232]
    float*  smax = (float*)(Ps + 64 * PSTR);  // [2][64]
    float*  ssum = smax + 2 * 64;             // [2][64]

    const int tid  = threadIdx.x;
    const int lane = tid & 31;
    const int wid  = tid >> 5;
    const int warp_m = wid >> 1;            // 0..3
    const int warp_n = wid & 1;             // 0..1

    const int tx0 = blockIdx.x * 8;
    const int ty0 = blockIdx.y * 8;
    const int z   = blockIdx.z;             // n*8 + g
    const int hy0 = min(max(ty0 - 3, 0), HW - 14);
    const int hx0 = min(max(tx0 - 3, 0), HW - 14);

    const __half* qp = qkv + (size_t)z * PLANE;
    const __half* kp = qkv + K_OFF + (size_t)z * PLANE;
    const __half* vp = qkv + V_OFF + (size_t)z * PLANE;

    // Zero pad rows (hx = 14,15) of Kh and Vh: 28 rows x 64 halves each.
    for (int i = tid; i < 28 * 8; i += 256) {
        const int p = i >> 3;
        const int r = (p >> 1) * 16 + 14 + (p & 1);
        const int c = (i & 7) * 8;
        *(float4*)&Kh[r * HSTR + c] = make_float4(0.f, 0.f, 0.f, 0.f);
        *(float4*)&Vh[r * HSTR + c] = make_float4(0.f, 0.f, 0.f, 0.f);
    }
    // Stage K/V halo: 196 valid rows x 8 chunks of 16B each.
    for (int i = tid; i < 196 * 8; i += 256) {
        const int pl = i >> 3;
        const int hy = pl / 14, hx = pl - hy * 14;
        const int r  = hy * 16 + hx;
        const int c  = (i & 7) * 8;
        const size_t gp = (size_t)((hy0 + hy) * HW + hx0 + hx) * 64 + c;
        cp_async16(&Kh[r * HSTR + c], kp + gp);
        cp_async16(&Vh[r * HSTR + c], vp + gp);
    }
    // Stage Q tile: 64 rows x 8 chunks.
    for (int i = tid; i < 64 * 8; i += 256) {
        const int pl = i >> 3;
        const int py = pl >> 3, px = pl & 7;
        const int c  = (i & 7) * 8;
        const size_t gp = (size_t)((ty0 + py) * HW + tx0 + px) * 64 + c;
        cp_async16(&Qs[pl * HSTR + c], qp + gp);
    }
    cp_commit();
    cp_wait<0>();
    __syncthreads();

    // ---- Phase 1: S = Q · K^T over this warp's n-half (112 cols = 14 n8-tiles)
    float sacc[14][4];
#pragma unroll
    for (int j = 0; j < 14; ++j)
#pragma unroll
        for (int c = 0; c < 4; ++c) sacc[j][c] = 0.f;

#pragma unroll
    for (int ks = 0; ks < 4; ++ks) {
        const int k0 = ks * 16;
        uint32_t aq[4];
        ldsm_x4(aq, Qs + (warp_m * 16 + (lane & 15)) * HSTR + k0 + ((lane >> 4) << 3));
#pragma unroll
        for (int u = 0; u < 7; ++u) {
            const int n0 = warp_n * 112 + u * 16;
            uint32_t kf[4];
            ldsm_x4(kf, Kh + (n0 + (lane & 7) + ((lane >> 4) & 1) * 8) * HSTR
                        + k0 + ((lane >> 3) & 1) * 8);
            mma16816(sacc[2 * u],     aq, kf[0], kf[1]);
            mma16816(sacc[2 * u + 1], aq, kf[2], kf[3]);
        }
    }

    // ---- Phase 2: mask + scale, row max
    const int px   = lane >> 2;                       // query x within tile
    const int qa   = warp_m * 16 + px;                // query idx (rows c0/c1)
    const int qb   = qa + 8;                          // rows c2/c3
    const int ya   = ty0 + 2 * warp_m;                // global y of qa
    const int yb   = ya + 1;
    const int syl_a = min(max(ya - 3, 0), HW - KS) - hy0;
    const int syl_b = min(max(yb - 3, 0), HW - KS) - hy0;
    const int sxl   = min(max(tx0 + px - 3, 0), HW - KS) - hx0;

    float ma = -1e30f, mb = -1e30f;
#pragma unroll
    for (int jt = 0; jt < 14; ++jt) {
        const int jg  = warp_n * 14 + jt;
        const int hy  = jg >> 1;
        const int hx0j = (jg & 1) * 8 + (lane & 3) * 2;
        const bool vya = (unsigned)(hy - syl_a) < 7u;
        const bool vyb = (unsigned)(hy - syl_b) < 7u;
        const bool vx0 = (unsigned)(hx0j - sxl) < 7u;
        const bool vx1 = (unsigned)(hx0j + 1 - sxl) < 7u;
        sacc[jt][0] = (vya && vx0) ? sacc[jt][0] * 0.125f : -1e30f;
        sacc[jt][1] = (vya && vx1) ? sacc[jt][1] * 0.125f : -1e30f;
        sacc[jt][2] = (vyb && vx0) ? sacc[jt][2] * 0.125f : -1e30f;
        sacc[jt][3] = (vyb && vx1) ? sacc[jt][3] * 0.125f : -1e30f;
        ma = fmaxf(ma, fmaxf(sacc[jt][0], sacc[jt][1]));
        mb = fmaxf(mb, fmaxf(sacc[jt][2], sacc[jt][3]));
    }
    // reduce across the 4 lanes of the quad (l&3)
    ma = fmaxf(ma, __shfl_xor_sync(0xffffffffu, ma, 1));
    ma = fmaxf(ma, __shfl_xor_sync(0xffffffffu, ma, 2));
    mb = fmaxf(mb, __shfl_xor_sync(0xffffffffu, mb, 1));
    mb = fmaxf(mb, __shfl_xor_sync(0xffffffffu, mb, 2));
    if ((lane & 3) == 0) {
        smax[warp_n * 64 + qa] = ma;
        smax[warp_n * 64 + qb] = mb;
    }
    __syncthreads();
    const float Ma = fmaxf(smax[qa], smax[64 + qa]);
    const float Mb = fmaxf(smax[qb], smax[64 + qb]);

    // ---- Phase 3: exp, row sums, P -> smem (fp16)
    float sa = 0.f, sb = 0.f;
#pragma unroll
    for (int jt = 0; jt < 14; ++jt) {
        const float p0 = __expf(sacc[jt][0] - Ma);
        const float p1 = __expf(sacc[jt][1] - Ma);
        const float p2 = __expf(sacc[jt][2] - Mb);
        const float p3 = __expf(sacc[jt][3] - Mb);
        sa += p0 + p1;
        sb += p2 + p3;
        const int col = warp_n * 112 + jt * 8 + (lane & 3) * 2;
        *(__half2*)&Ps[qa * PSTR + col] = __floats2half2_rn(p0, p1);
        *(__half2*)&Ps[qb * PSTR + col] = __floats2half2_rn(p2, p3);
    }
    sa += __shfl_xor_sync(0xffffffffu, sa, 1);
    sa += __shfl_xor_sync(0xffffffffu, sa, 2);
    sb += __shfl_xor_sync(0xffffffffu, sb, 1);
    sb += __shfl_xor_sync(0xffffffffu, sb, 2);
    if ((lane & 3) == 0) {
        ssum[warp_n * 64 + qa] = sa;
        ssum[warp_n * 64 + qb] = sb;
    }
    __syncthreads();

    // ---- Phase 4: O = P · V over this warp's n-half of dims (32 cols)
    float oacc[4][4];
#pragma unroll
    for (int nt = 0; nt < 4; ++nt)
#pragma unroll
        for (int c = 0; c < 4; ++c) oacc[nt][c] = 0.f;

#pragma unroll
    for (int t = 0; t < 14; ++t) {
        const int k0 = t * 16;
        uint32_t ap[4];
        ldsm_x4(ap, Ps + (warp_m * 16 + (lane & 15)) * PSTR + k0 + ((lane >> 4) << 3));
        const __half* vbase = Vh + (k0 + ((lane >> 3) & 1) * 8 + (lane & 7)) * HSTR
                                 + warp_n * 32 + ((lane >> 4) << 3);
#pragma unroll
        for (int nb = 0; nb < 2; ++nb) {
            uint32_t vf[4];
            ldsm_x4t(vf, vbase + nb * 16);
            mma16816(oacc[nb * 2],     ap, vf[0], vf[1]);
            mma16816(oacc[nb * 2 + 1], ap, vf[2], vf[3]);
        }
    }

    // ---- Epilogue: normalize by row sums, write att (fp16, pixel-major)
    const float inva = 1.f / (ssum[qa] + ssum[64 + qa]);
    const float invb = 1.f / (ssum[qb] + ssum[64 + qb]);
    const int n = z >> 3;
    const int g = z & 7;
    const int gx = tx0 + px;
    const size_t rowa = ((size_t)n * IMG_PIX + ya * HW + gx) * D_MODEL + g * D_HEAD;
    const size_t rowb = ((size_t)n * IMG_PIX + yb * HW + gx) * D_MODEL + g * D_HEAD;
#pragma unroll
    for (int nt = 0; nt < 4; ++nt) {
        const int col = warp_n * 32 + nt * 8 + (lane & 3) * 2;
        *(__half2*)&out[rowa + col] =
            __floats2half2_rn(oacc[nt][0] * inva, oacc[nt][1] * inva);
        *(__half2*)&out[rowb + col] =
            __floats2half2_rn(oacc[nt][2] * invb, oacc[nt][3] * invb);
    }
}

// ---------------------------------------------------------------------------
extern "C" void kernel_launch(void* const* d_in, const int* in_sizes, int n_in,
                              void* d_out, int out_size) {
    const float* x     = (const float*)d_in[0];
    const float* w_qkv = (const float*)d_in[1];
    const float* w_out = (const float*)d_in[2];
    float* out = (float*)d_out;

    __half *xh, *wqkvh, *wouth, *qkvh, *atth;
    cudaGetSymbolAddress((void**)&xh, g_xh);
    cudaGetSymbolAddress((void**)&wqkvh, g_wqkvh);
    cudaGetSymbolAddress((void**)&wouth, g_wouth);
    cudaGetSymbolAddress((void**)&qkvh, g_qkvh);
    cudaGetSymbolAddress((void**)&atth, g_atth);

    const int hsmem = 2 * HSTAGE * sizeof(__half);
    static bool attr_set = false;
    if (!attr_set) {
        cudaFuncSetAttribute(hgemm<true>,  cudaFuncAttributeMaxDynamicSharedMemorySize, hsmem);
        cudaFuncSetAttribute(hgemm<false>, cudaFuncAttributeMaxDynamicSharedMemorySize, hsmem);
        cudaFuncSetAttribute(natten5, cudaFuncAttributeMaxDynamicSharedMemorySize, (int)NAT5_SMEM);
        attr_set = true;
    }

    // 0) Convert inputs to fp16
    const int NX = M_TOTAL * D_MODEL, NWQ = D_MODEL * QKV_N, NWO = D_MODEL * D_MODEL;
    const int tot4 = (NX + NWQ + NWO) / 4;
    cvt3<<<(tot4 + 255) / 256, 256>>>(x, xh, NX, w_qkv, wqkvh, NWQ, w_out, wouth, NWO);

    // 1) QKV projection with plane-scatter epilogue
    hgemm<true><<<dim3(QKV_N / 128, M_TOTAL / 128), 256, hsmem>>>(
        xh, wqkvh, qkvh, M_TOTAL, QKV_N, D_MODEL);

    // 2) Dense masked neighborhood attention on tensor cores
    natten5<<<dim3(HW / 8, HW / 8, 2 * N_HEADS), 256, NAT5_SMEM>>>(qkvh, atth);

    // 3) Output projection -> fp32 output
    hgemm<false><<<dim3(D_MODEL / 128, M_TOTAL / 128), 256, hsmem>>>(
        atth, wouth, out, M_TOTAL, D_MODEL, D_MODEL);
}

// round 7
// speedup vs baseline: 6.0410x; 1.0708x over previous
#include <cuda_runtime.h>
#include <cuda_fp16.h>
#include <cstdint>

#define M_TOTAL 4608          // 2 * 48 * 48 pixels
#define D_MODEL 512
#define QKV_N   1536
#define N_HEADS 8
#define D_HEAD  64
#define KS      7
#define HW      48
#define IMG_PIX (HW * HW)     // 2304
#define PLANE   (IMG_PIX * D_HEAD)

// fp16 scratch (device globals)
__device__ __half g_xh[M_TOTAL * D_MODEL];
__device__ __half g_wqkvh[D_MODEL * QKV_N];
__device__ __half g_wouth[D_MODEL * D_MODEL];
__device__ __half g_qkvh[M_TOTAL * QKV_N];   // q planes | k planes | v planes
__device__ __half g_atth[M_TOTAL * D_MODEL];

#define K_OFF ((size_t)M_TOTAL * 512)
#define V_OFF ((size_t)M_TOTAL * 1024)

// ---------------------------------------------------------------------------
__device__ __forceinline__ void cp_async16(void* smem_dst, const void* gmem_src) {
    unsigned s = (unsigned)__cvta_generic_to_shared(smem_dst);
    asm volatile("cp.async.cg.shared.global [%0], [%1], 16;" :: "r"(s), "l"(gmem_src));
}
__device__ __forceinline__ void cp_commit() { asm volatile("cp.async.commit_group;"); }
template <int N>
__device__ __forceinline__ void cp_wait() { asm volatile("cp.async.wait_group %0;" :: "n"(N)); }

__device__ __forceinline__ void ldsm_x4(uint32_t r[4], const __half* p) {
    uint32_t a = (uint32_t)__cvta_generic_to_shared(p);
    asm volatile("ldmatrix.sync.aligned.m8n8.x4.shared.b16 {%0,%1,%2,%3}, [%4];"
                 : "=r"(r[0]), "=r"(r[1]), "=r"(r[2]), "=r"(r[3]) : "r"(a));
}
__device__ __forceinline__ void ldsm_x4t(uint32_t r[4], const __half* p) {
    uint32_t a = (uint32_t)__cvta_generic_to_shared(p);
    asm volatile("ldmatrix.sync.aligned.m8n8.x4.trans.shared.b16 {%0,%1,%2,%3}, [%4];"
                 : "=r"(r[0]), "=r"(r[1]), "=r"(r[2]), "=r"(r[3]) : "r"(a));
}
__device__ __forceinline__ void mma16816(float c[4], const uint32_t a[4],
                                         uint32_t b0, uint32_t b1) {
    asm volatile(
        "mma.sync.aligned.m16n8k16.row.col.f32.f16.f16.f32 "
        "{%0,%1,%2,%3}, {%4,%5,%6,%7}, {%8,%9}, {%0,%1,%2,%3};"
        : "+f"(c[0]), "+f"(c[1]), "+f"(c[2]), "+f"(c[3])
        : "r"(a[0]), "r"(a[1]), "r"(a[2]), "r"(a[3]), "r"(b0), "r"(b1));
}

// ---------------------------------------------------------------------------
// Fused f32 -> f16 conversion for three arrays.
// ---------------------------------------------------------------------------
__global__ void cvt3(const float* __restrict__ s0, __half* __restrict__ d0, int n0,
                     const float* __restrict__ s1, __half* __restrict__ d1, int n1,
                     const float* __restrict__ s2, __half* __restrict__ d2, int n2) {
    int i = blockIdx.x * blockDim.x + threadIdx.x;
    const int t0 = n0 >> 2, t1 = t0 + (n1 >> 2), t2 = t1 + (n2 >> 2);
    const float* s; __half* d; int j;
    if (i < t0)      { s = s0; d = d0; j = i; }
    else if (i < t1) { s = s1; d = d1; j = i - t0; }
    else if (i < t2) { s = s2; d = d2; j = i - t1; }
    else return;
    float4 v = ((const float4*)s)[j];
    ((__half2*)d)[j * 2]     = __floats2half2_rn(v.x, v.y);
    ((__half2*)d)[j * 2 + 1] = __floats2half2_rn(v.z, v.w);
}

// ---------------------------------------------------------------------------
// fp16 GEMM: 128x128x32 tile, mma.m16n8k16 + ldmatrix, 4-stage cp.async ring.
// ---------------------------------------------------------------------------
#define HA_STR 40
#define HB_STR 136
#define HSTAGE (128 * HA_STR + 32 * HB_STR)   // 9472 halves = 18944 B
#define STAGES 4

template <bool SCATTER>
__global__ __launch_bounds__(256, 2) void hgemm(const __half* __restrict__ A,
                                                const __half* __restrict__ B,
                                                void* __restrict__ Cv,
                                                int M, int N, int K) {
    extern __shared__ __half hsm[];

    const int t      = threadIdx.x;
    const int lane   = t & 31;
    const int wid    = t >> 5;
    const int warp_m = wid >> 1;
    const int warp_n = wid & 1;
    const int c_lane = lane & 3;
    const int r_lane = lane >> 2;

    const int row0 = blockIdx.y * 128;
    const int col0 = blockIdx.x * 128;
    const int NT = K / 32;

    auto load_tile = [&](int tile, int stage) {
        __half* As = hsm + stage * HSTAGE;
        __half* Bs = As + 128 * HA_STR;
        const __half* gA = A + (size_t)row0 * K + tile * 32;
        const __half* gB = B + (size_t)(tile * 32) * N + col0;
#pragma unroll
        for (int u = 0; u < 2; ++u) {
            int i = t + u * 256;
            int arow = i >> 2, acol = (i & 3) * 8;
            cp_async16(&As[arow * HA_STR + acol], gA + (size_t)arow * K + acol);
        }
#pragma unroll
        for (int u = 0; u < 2; ++u) {
            int i = t + u * 256;
            int brow = i >> 4, bcol = (i & 15) * 8;
            cp_async16(&Bs[brow * HB_STR + bcol], gB + (size_t)brow * N + bcol);
        }
        cp_commit();
    };

    float acc[2][8][4];
#pragma unroll
    for (int mt = 0; mt < 2; ++mt)
#pragma unroll
        for (int nt = 0; nt < 8; ++nt)
#pragma unroll
            for (int j = 0; j < 4; ++j) acc[mt][nt][j] = 0.f;

    // Prologue: fill STAGES-1 stages
#pragma unroll
    for (int p = 0; p < STAGES - 1; ++p) {
        if (p < NT) load_tile(p, p);
        else cp_commit();
    }

    for (int tile = 0; tile < NT; ++tile) {
        cp_wait<STAGES - 2>();
        __syncthreads();

        const __half* As = hsm + (tile % STAGES) * HSTAGE;
        const __half* Bs = As + 128 * HA_STR;

#pragma unroll
        for (int ks = 0; ks < 2; ++ks) {
            const int k0 = ks * 16;
            uint32_t af[2][4];
            const __half* ap = As + (warp_m * 32 + (lane & 15)) * HA_STR
                                  + k0 + ((lane >> 4) << 3);
            ldsm_x4(af[0], ap);
            ldsm_x4(af[1], ap + 16 * HA_STR);
            uint32_t bf[4][4];
            const __half* bp = Bs + (k0 + ((lane >> 3) & 1) * 8 + (lane & 7)) * HB_STR
                                  + warp_n * 64 + (lane >> 4) * 8;
#pragma unroll
            for (int nb = 0; nb < 4; ++nb)
                ldsm_x4t(bf[nb], bp + nb * 16);
#pragma unroll
            for (int mt = 0; mt < 2; ++mt)
#pragma unroll
                for (int nt = 0; nt < 8; ++nt)
                    mma16816(acc[mt][nt], af[mt],
                             bf[nt >> 1][(nt & 1) * 2], bf[nt >> 1][(nt & 1) * 2 + 1]);
        }

        // Issue next load into the stage whose last read finished one barrier ago
        const int nxt = tile + STAGES - 1;
        if (nxt < NT) load_tile(nxt, nxt % STAGES);
        else cp_commit();
    }

    const int img_n = row0 >= IMG_PIX;
#pragma unroll
    for (int mt = 0; mt < 2; ++mt) {
        const int row_g = row0 + warp_m * 32 + mt * 16 + r_lane;
#pragma unroll
        for (int nt = 0; nt < 8; ++nt) {
            const int col_g = col0 + warp_n * 64 + nt * 8 + 2 * c_lane;
            if (!SCATTER) {
                float* C = (float*)Cv;
                *(float2*)&C[(size_t)row_g * N + col_g] =
                    make_float2(acc[mt][nt][0], acc[mt][nt][1]);
                *(float2*)&C[(size_t)(row_g + 8) * N + col_g] =
                    make_float2(acc[mt][nt][2], acc[mt][nt][3]);
            } else {
                __half* C = (__half*)Cv;
                const int which = col_g >> 9;
                const int g     = (col_g >> 6) & 7;
                const int e     = col_g & 63;
                const int p     = row_g - img_n * IMG_PIX;
                __half* dst = C + (size_t)which * K_OFF +
                              ((size_t)(img_n * 8 + g) * IMG_PIX + p) * 64 + e;
                *(__half2*)dst = __floats2half2_rn(acc[mt][nt][0], acc[mt][nt][1]);
                *(__half2*)(dst + 8 * 64) = __floats2half2_rn(acc[mt][nt][2], acc[mt][nt][3]);
            }
        }
    }
}

// ---------------------------------------------------------------------------
// natten5: dense masked attention on tensor cores (unchanged from R6).
// ---------------------------------------------------------------------------
#define HN   224
#define HSTR 72
#define PSTR 232
#define NAT5_SMEM ((2 * HN * HSTR + 64 * HSTR + 64 * PSTR) * sizeof(__half) \
                   + 4 * 64 * sizeof(float))

__global__ __launch_bounds__(256) void natten5(const __half* __restrict__ qkv,
                                               __half* __restrict__ out) {
    extern __shared__ __half shh[];
    __half* Kh = shh;                       // [224][72]
    __half* Vh = Kh + HN * HSTR;            // [224][72]
    __half* Qs = Vh + HN * HSTR;            // [64][72]
    __half* Ps = Qs + 64 * HSTR;            // [64][232]
    float*  smax = (float*)(Ps + 64 * PSTR);
    float*  ssum = smax + 2 * 64;

    const int tid  = threadIdx.x;
    const int lane = tid & 31;
    const int wid  = tid >> 5;
    const int warp_m = wid >> 1;
    const int warp_n = wid & 1;

    const int tx0 = blockIdx.x * 8;
    const int ty0 = blockIdx.y * 8;
    const int z   = blockIdx.z;
    const int hy0 = min(max(ty0 - 3, 0), HW - 14);
    const int hx0 = min(max(tx0 - 3, 0), HW - 14);

    const __half* qp = qkv + (size_t)z * PLANE;
    const __half* kp = qkv + K_OFF + (size_t)z * PLANE;
    const __half* vp = qkv + V_OFF + (size_t)z * PLANE;

    for (int i = tid; i < 28 * 8; i += 256) {
        const int p = i >> 3;
        const int r = (p >> 1) * 16 + 14 + (p & 1);
        const int c = (i & 7) * 8;
        *(float4*)&Kh[r * HSTR + c] = make_float4(0.f, 0.f, 0.f, 0.f);
        *(float4*)&Vh[r * HSTR + c] = make_float4(0.f, 0.f, 0.f, 0.f);
    }
    for (int i = tid; i < 196 * 8; i += 256) {
        const int pl = i >> 3;
        const int hy = pl / 14, hx = pl - hy * 14;
        const int r  = hy * 16 + hx;
        const int c  = (i & 7) * 8;
        const size_t gp = (size_t)((hy0 + hy) * HW + hx0 + hx) * 64 + c;
        cp_async16(&Kh[r * HSTR + c], kp + gp);
        cp_async16(&Vh[r * HSTR + c], vp + gp);
    }
    for (int i = tid; i < 64 * 8; i += 256) {
        const int pl = i >> 3;
        const int py = pl >> 3, px = pl & 7;
        const int c  = (i & 7) * 8;
        const size_t gp = (size_t)((ty0 + py) * HW + tx0 + px) * 64 + c;
        cp_async16(&Qs[pl * HSTR + c], qp + gp);
    }
    cp_commit();
    cp_wait<0>();
    __syncthreads();

    float sacc[14][4];
#pragma unroll
    for (int j = 0; j < 14; ++j)
#pragma unroll
        for (int c = 0; c < 4; ++c) sacc[j][c] = 0.f;

#pragma unroll
    for (int ks = 0; ks < 4; ++ks) {
        const int k0 = ks * 16;
        uint32_t aq[4];
        ldsm_x4(aq, Qs + (warp_m * 16 + (lane & 15)) * HSTR + k0 + ((lane >> 4) << 3));
#pragma unroll
        for (int u = 0; u < 7; ++u) {
            const int n0 = warp_n * 112 + u * 16;
            uint32_t kf[4];
            ldsm_x4(kf, Kh + (n0 + (lane & 7) + ((lane >> 4) & 1) * 8) * HSTR
                        + k0 + ((lane >> 3) & 1) * 8);
            mma16816(sacc[2 * u],     aq, kf[0], kf[1]);
            mma16816(sacc[2 * u + 1], aq, kf[2], kf[3]);
        }
    }

    const int px   = lane >> 2;
    const int qa   = warp_m * 16 + px;
    const int qb   = qa + 8;
    const int ya   = ty0 + 2 * warp_m;
    const int yb   = ya + 1;
    const int syl_a = min(max(ya - 3, 0), HW - KS) - hy0;
    const int syl_b = min(max(yb - 3, 0), HW - KS) - hy0;
    const int sxl   = min(max(tx0 + px - 3, 0), HW - KS) - hx0;

    float ma = -1e30f, mb = -1e30f;
#pragma unroll
    for (int jt = 0; jt < 14; ++jt) {
        const int jg  = warp_n * 14 + jt;
        const int hy  = jg >> 1;
        const int hx0j = (jg & 1) * 8 + (lane & 3) * 2;
        const bool vya = (unsigned)(hy - syl_a) < 7u;
        const bool vyb = (unsigned)(hy - syl_b) < 7u;
        const bool vx0 = (unsigned)(hx0j - sxl) < 7u;
        const bool vx1 = (unsigned)(hx0j + 1 - sxl) < 7u;
        sacc[jt][0] = (vya && vx0) ? sacc[jt][0] * 0.125f : -1e30f;
        sacc[jt][1] = (vya && vx1) ? sacc[jt][1] * 0.125f : -1e30f;
        sacc[jt][2] = (vyb && vx0) ? sacc[jt][2] * 0.125f : -1e30f;
        sacc[jt][3] = (vyb && vx1) ? sacc[jt][3] * 0.125f : -1e30f;
        ma = fmaxf(ma, fmaxf(sacc[jt][0], sacc[jt][1]));
        mb = fmaxf(mb, fmaxf(sacc[jt][2], sacc[jt][3]));
    }
    ma = fmaxf(ma, __shfl_xor_sync(0xffffffffu, ma, 1));
    ma = fmaxf(ma, __shfl_xor_sync(0xffffffffu, ma, 2));
    mb = fmaxf(mb, __shfl_xor_sync(0xffffffffu, mb, 1));
    mb = fmaxf(mb, __shfl_xor_sync(0xffffffffu, mb, 2));
    if ((lane & 3) == 0) {
        smax[warp_n * 64 + qa] = ma;
        smax[warp_n * 64 + qb] = mb;
    }
    __syncthreads();
    const float Ma = fmaxf(smax[qa], smax[64 + qa]);
    const float Mb = fmaxf(smax[qb], smax[64 + qb]);

    float sa = 0.f, sb = 0.f;
#pragma unroll
    for (int jt = 0; jt < 14; ++jt) {
        const float p0 = __expf(sacc[jt][0] - Ma);
        const float p1 = __expf(sacc[jt][1] - Ma);
        const float p2 = __expf(sacc[jt][2] - Mb);
        const float p3 = __expf(sacc[jt][3] - Mb);
        sa += p0 + p1;
        sb += p2 + p3;
        const int col = warp_n * 112 + jt * 8 + (lane & 3) * 2;
        *(__half2*)&Ps[qa * PSTR + col] = __floats2half2_rn(p0, p1);
        *(__half2*)&Ps[qb * PSTR + col] = __floats2half2_rn(p2, p3);
    }
    sa += __shfl_xor_sync(0xffffffffu, sa, 1);
    sa += __shfl_xor_sync(0xffffffffu, sa, 2);
    sb += __shfl_xor_sync(0xffffffffu, sb, 1);
    sb += __shfl_xor_sync(0xffffffffu, sb, 2);
    if ((lane & 3) == 0) {
        ssum[warp_n * 64 + qa] = sa;
        ssum[warp_n * 64 + qb] = sb;
    }
    __syncthreads();

    float oacc[4][4];
#pragma unroll
    for (int nt = 0; nt < 4; ++nt)
#pragma unroll
        for (int c = 0; c < 4; ++c) oacc[nt][c] = 0.f;

#pragma unroll
    for (int t = 0; t < 14; ++t) {
        const int k0 = t * 16;
        uint32_t ap[4];
        ldsm_x4(ap, Ps + (warp_m * 16 + (lane & 15)) * PSTR + k0 + ((lane >> 4) << 3));
        const __half* vbase = Vh + (k0 + ((lane >> 3) & 1) * 8 + (lane & 7)) * HSTR
                                 + warp_n * 32 + ((lane >> 4) << 3);
#pragma unroll
        for (int nb = 0; nb < 2; ++nb) {
            uint32_t vf[4];
            ldsm_x4t(vf, vbase + nb * 16);
            mma16816(oacc[nb * 2],     ap, vf[0], vf[1]);
            mma16816(oacc[nb * 2 + 1], ap, vf[2], vf[3]);
        }
    }

    const float inva = 1.f / (ssum[qa] + ssum[64 + qa]);
    const float invb = 1.f / (ssum[qb] + ssum[64 + qb]);
    const int n = z >> 3;
    const int g = z & 7;
    const int gx = tx0 + px;
    const size_t rowa = ((size_t)n * IMG_PIX + ya * HW + gx) * D_MODEL + g * D_HEAD;
    const size_t rowb = ((size_t)n * IMG_PIX + yb * HW + gx) * D_MODEL + g * D_HEAD;
#pragma unroll
    for (int nt = 0; nt < 4; ++nt) {
        const int col = warp_n * 32 + nt * 8 + (lane & 3) * 2;
        *(__half2*)&out[rowa + col] =
            __floats2half2_rn(oacc[nt][0] * inva, oacc[nt][1] * inva);
        *(__half2*)&out[rowb + col] =
            __floats2half2_rn(oacc[nt][2] * invb, oacc[nt][3] * invb);
    }
}

// ---------------------------------------------------------------------------
extern "C" void kernel_launch(void* const* d_in, const int* in_sizes, int n_in,
                              void* d_out, int out_size) {
    const float* x     = (const float*)d_in[0];
    const float* w_qkv = (const float*)d_in[1];
    const float* w_out = (const float*)d_in[2];
    float* out = (float*)d_out;

    __half *xh, *wqkvh, *wouth, *qkvh, *atth;
    cudaGetSymbolAddress((void**)&xh, g_xh);
    cudaGetSymbolAddress((void**)&wqkvh, g_wqkvh);
    cudaGetSymbolAddress((void**)&wouth, g_wouth);
    cudaGetSymbolAddress((void**)&qkvh, g_qkvh);
    cudaGetSymbolAddress((void**)&atth, g_atth);

    const int hsmem = STAGES * HSTAGE * sizeof(__half);   // 75776
    static bool attr_set = false;
    if (!attr_set) {
        cudaFuncSetAttribute(hgemm<true>,  cudaFuncAttributeMaxDynamicSharedMemorySize, hsmem);
        cudaFuncSetAttribute(hgemm<false>, cudaFuncAttributeMaxDynamicSharedMemorySize, hsmem);
        cudaFuncSetAttribute(natten5, cudaFuncAttributeMaxDynamicSharedMemorySize, (int)NAT5_SMEM);
        attr_set = true;
    }

    // 0) Convert inputs to fp16
    const int NX = M_TOTAL * D_MODEL, NWQ = D_MODEL * QKV_N, NWO = D_MODEL * D_MODEL;
    const int tot4 = (NX + NWQ + NWO) / 4;
    cvt3<<<(tot4 + 255) / 256, 256>>>(x, xh, NX, w_qkv, wqkvh, NWQ, w_out, wouth, NWO);

    // 1) QKV projection with plane-scatter epilogue
    hgemm<true><<<dim3(QKV_N / 128, M_TOTAL / 128), 256, hsmem>>>(
        xh, wqkvh, qkvh, M_TOTAL, QKV_N, D_MODEL);

    // 2) Dense masked neighborhood attention on tensor cores
    natten5<<<dim3(HW / 8, HW / 8, 2 * N_HEADS), 256, NAT5_SMEM>>>(qkvh, atth);

    // 3) Output projection -> fp32 output
    hgemm<false><<<dim3(D_MODEL / 128, M_TOTAL / 128), 256, hsmem>>>(
        atth, wouth, out, M_TOTAL, D_MODEL, D_MODEL);
}